// round 3
// baseline (speedup 1.0000x reference)
#include <cuda_runtime.h>

#define BB   4
#define NN   2048
#define DD   64
#define HH   8
#define BH   (BB*HH)      // 32
#define TOK  (BB*NN)      // 8192
#define VD   124
#define VDP  128
#define OUTD (HH*VD)      // 992

// ---------------- scratch (no dynamic allocation allowed) ----------------
__device__ float g_q[(size_t)BH*NN*DD];      // [b][h][n][d]   16 MB
__device__ float g_k[(size_t)BH*NN*DD];      // [b][h][n][d]   16 MB
__device__ float g_v[(size_t)TOK*VDP];       // [b*N+n][c]      4 MB (padded to 128)
__device__ float g_outh[(size_t)TOK*OUTD];   // [b*N+n][h*124+c] 32.5 MB

// ---------------------------------------------------------------
// K1: qk = x @ W_qk^T, scatter to q/k in (b,h,n,d) layout.
// x: (8192,64), W_qk: (1024,64). Tile 64x64, 256 thr, 4x4/thread.
// ---------------------------------------------------------------
__global__ __launch_bounds__(256) void k_qkproj(const float* __restrict__ x,
                                                const float* __restrict__ Wqk) {
    __shared__ float Xs[64][68];   // [d][n_local]
    __shared__ float Ws[64][68];   // [d][m_local]
    const int tid = threadIdx.x;
    const int m0 = blockIdx.x * 64;
    const int n0 = blockIdx.y * 64;
    const int r  = tid >> 4;
    const int c4 = (tid & 15) << 2;
    #pragma unroll
    for (int p = 0; p < 4; ++p) {
        const int rr = r + p * 16;
        float4 a = *(const float4*)&x[(size_t)(n0 + rr) * 64 + c4];
        Xs[c4+0][rr] = a.x; Xs[c4+1][rr] = a.y; Xs[c4+2][rr] = a.z; Xs[c4+3][rr] = a.w;
        float4 w = *(const float4*)&Wqk[(size_t)(m0 + rr) * 64 + c4];
        Ws[c4+0][rr] = w.x; Ws[c4+1][rr] = w.y; Ws[c4+2][rr] = w.z; Ws[c4+3][rr] = w.w;
    }
    __syncthreads();
    const int ty = tid >> 4, tx = tid & 15;
    float acc[4][4] = {};
    #pragma unroll
    for (int d = 0; d < 64; ++d) {
        float4 a = *(const float4*)&Xs[d][ty * 4];
        float4 b = *(const float4*)&Ws[d][tx * 4];
        acc[0][0] += a.x*b.x; acc[0][1] += a.x*b.y; acc[0][2] += a.x*b.z; acc[0][3] += a.x*b.w;
        acc[1][0] += a.y*b.x; acc[1][1] += a.y*b.y; acc[1][2] += a.y*b.z; acc[1][3] += a.y*b.w;
        acc[2][0] += a.z*b.x; acc[2][1] += a.z*b.y; acc[2][2] += a.z*b.z; acc[2][3] += a.z*b.w;
        acc[3][0] += a.w*b.x; acc[3][1] += a.w*b.y; acc[3][2] += a.w*b.z; acc[3][3] += a.w*b.w;
    }
    #pragma unroll
    for (int ii = 0; ii < 4; ++ii) {
        const int n = n0 + ty * 4 + ii;
        const int b = n >> 11, nl = n & 2047;
        #pragma unroll
        for (int jj = 0; jj < 4; ++jj) {
            int m = m0 + tx * 4 + jj;
            float* dst = g_q;
            if (m >= 512) { dst = g_k; m -= 512; }
            const int h = m >> 6, dd = m & 63;
            dst[((size_t)(b * HH + h) * NN + nl) * 64 + dd] = acc[ii][jj];
        }
    }
}

// ---------------------------------------------------------------
// K2: value conv chain: per token 64 -> (2,40) -> (4,31) = 124 vals.
// ---------------------------------------------------------------
__global__ __launch_bounds__(128) void k_conv(const float* __restrict__ x,
                                              const float* __restrict__ w1, const float* __restrict__ b1,
                                              const float* __restrict__ w2, const float* __restrict__ b2) {
    __shared__ float xr[64];
    __shared__ float h1s[2][40];
    const int n = blockIdx.x;
    const int tid = threadIdx.x;
    if (tid < 64) xr[tid] = x[(size_t)n * 64 + tid];
    __syncthreads();
    if (tid < 80) {
        const int c = tid / 40, t = tid % 40;
        float acc = b1[c];
        #pragma unroll
        for (int k = 0; k < 25; ++k) acc += xr[t + k] * w1[c * 25 + k];
        h1s[c][t] = acc;
    }
    __syncthreads();
    if (tid < 124) {
        const int c2 = tid / 31, t2 = tid % 31;
        float acc = b2[c2];
        #pragma unroll
        for (int c = 0; c < 2; ++c)
            #pragma unroll
            for (int k = 0; k < 10; ++k)
                acc += h1s[c][t2 + k] * w2[(c2 * 2 + c) * 10 + k];
        g_v[(size_t)n * VDP + tid] = acc;
    } else {
        g_v[(size_t)n * VDP + tid] = 0.f;   // pad cols 124..127
    }
}

// ---------------------------------------------------------------
// K3: scores = scale * Q K^T, per (b,h). Tile 64x64, 4x4/thread.
// Writes (unnormalized-softmax) scaled scores into attn output region.
// ---------------------------------------------------------------
__global__ __launch_bounds__(256) void k_scores(float* __restrict__ attn) {
    __shared__ float Qs[64][68];
    __shared__ float Ks[64][68];
    const int bh = blockIdx.z;
    const int i0 = blockIdx.y * 64, j0 = blockIdx.x * 64;
    const float* qb = g_q + (size_t)bh * NN * 64;
    const float* kb = g_k + (size_t)bh * NN * 64;
    const int tid = threadIdx.x;
    const int r = tid >> 4, c4 = (tid & 15) << 2;
    #pragma unroll
    for (int p = 0; p < 4; ++p) {
        const int rr = r + p * 16;
        float4 a = *(const float4*)&qb[(size_t)(i0 + rr) * 64 + c4];
        Qs[c4+0][rr] = a.x; Qs[c4+1][rr] = a.y; Qs[c4+2][rr] = a.z; Qs[c4+3][rr] = a.w;
        float4 b = *(const float4*)&kb[(size_t)(j0 + rr) * 64 + c4];
        Ks[c4+0][rr] = b.x; Ks[c4+1][rr] = b.y; Ks[c4+2][rr] = b.z; Ks[c4+3][rr] = b.w;
    }
    __syncthreads();
    const int ty = tid >> 4, tx = tid & 15;
    float acc[4][4] = {};
    #pragma unroll
    for (int d = 0; d < 64; ++d) {
        float4 a = *(const float4*)&Qs[d][ty * 4];
        float4 b = *(const float4*)&Ks[d][tx * 4];
        acc[0][0] += a.x*b.x; acc[0][1] += a.x*b.y; acc[0][2] += a.x*b.z; acc[0][3] += a.x*b.w;
        acc[1][0] += a.y*b.x; acc[1][1] += a.y*b.y; acc[1][2] += a.y*b.z; acc[1][3] += a.y*b.w;
        acc[2][0] += a.z*b.x; acc[2][1] += a.z*b.y; acc[2][2] += a.z*b.z; acc[2][3] += a.z*b.w;
        acc[3][0] += a.w*b.x; acc[3][1] += a.w*b.y; acc[3][2] += a.w*b.z; acc[3][3] += a.w*b.w;
    }
    const float scale = 0.125f;   // 64^-0.5
    #pragma unroll
    for (int ii = 0; ii < 4; ++ii) {
        float4 o;
        o.x = acc[ii][0]*scale; o.y = acc[ii][1]*scale; o.z = acc[ii][2]*scale; o.w = acc[ii][3]*scale;
        *(float4*)&attn[((size_t)bh * NN + (i0 + ty*4 + ii)) * NN + j0 + tx*4] = o;
    }
}

// ---------------------------------------------------------------
// K4: row softmax in place, one block (256 thr) per row of 2048.
// ---------------------------------------------------------------
__global__ __launch_bounds__(256) void k_softmax(float* __restrict__ attn) {
    __shared__ float red[8];
    const size_t row = blockIdx.x;
    float* p = attn + row * (size_t)NN;
    const int tid = threadIdx.x;
    float v[8];
    #pragma unroll
    for (int e = 0; e < 8; ++e) v[e] = p[tid + e * 256];
    float m = v[0];
    #pragma unroll
    for (int e = 1; e < 8; ++e) m = fmaxf(m, v[e]);
    #pragma unroll
    for (int o = 16; o; o >>= 1) m = fmaxf(m, __shfl_xor_sync(0xffffffffu, m, o));
    if ((tid & 31) == 0) red[tid >> 5] = m;
    __syncthreads();
    float bm = red[0];
    #pragma unroll
    for (int w = 1; w < 8; ++w) bm = fmaxf(bm, red[w]);
    __syncthreads();
    float s = 0.f;
    #pragma unroll
    for (int e = 0; e < 8; ++e) { v[e] = __expf(v[e] - bm); s += v[e]; }
    #pragma unroll
    for (int o = 16; o; o >>= 1) s += __shfl_xor_sync(0xffffffffu, s, o);
    if ((tid & 31) == 0) red[tid >> 5] = s;
    __syncthreads();
    float bs = 0.f;
    #pragma unroll
    for (int w = 0; w < 8; ++w) bs += red[w];
    const float inv = 1.f / bs;
    #pragma unroll
    for (int e = 0; e < 8; ++e) p[tid + e * 256] = v[e] * inv;
}

// ---------------------------------------------------------------
// K5: out_head = attn @ v per (b,h). Output tile 64 x 128 (cols padded),
// k-tile 32, 256 thr, 4 rows x 8 cols per thread.
// ---------------------------------------------------------------
__global__ __launch_bounds__(256) void k_av(const float* __restrict__ attn) {
    __shared__ float As[32][68];   // [k][i]
    __shared__ float Vs[32][VDP];  // [k][c]
    const int bh = blockIdx.y;
    const int b = bh >> 3, h = bh & 7;
    const int i0 = blockIdx.x * 64;
    const float* Ab = attn + (size_t)bh * NN * NN + (size_t)i0 * NN;
    const float* Vb = g_v + (size_t)b * NN * VDP;
    const int tid = threadIdx.x;
    const int ty = tid >> 4, tx = tid & 15;
    const int ar = tid >> 3, ac4 = (tid & 7) << 2;     // A loader: i=ar(+32), k=ac4
    const int vr = tid >> 5, vc4 = (tid & 31) << 2;    // V loader: k=vr(+8),  c=vc4
    float acc[4][8] = {};
    for (int k0 = 0; k0 < NN; k0 += 32) {
        #pragma unroll
        for (int p = 0; p < 2; ++p) {
            const int rr = ar + p * 32;
            float4 a = *(const float4*)&Ab[(size_t)rr * NN + k0 + ac4];
            As[ac4+0][rr] = a.x; As[ac4+1][rr] = a.y; As[ac4+2][rr] = a.z; As[ac4+3][rr] = a.w;
        }
        #pragma unroll
        for (int p = 0; p < 4; ++p) {
            const int rr = vr + p * 8;
            *(float4*)&Vs[rr][vc4] = *(const float4*)&Vb[(size_t)(k0 + rr) * VDP + vc4];
        }
        __syncthreads();
        #pragma unroll
        for (int k = 0; k < 32; ++k) {
            float4 a  = *(const float4*)&As[k][ty * 4];
            float4 v0 = *(const float4*)&Vs[k][tx * 4];
            float4 v1 = *(const float4*)&Vs[k][64 + tx * 4];
            acc[0][0]+=a.x*v0.x; acc[0][1]+=a.x*v0.y; acc[0][2]+=a.x*v0.z; acc[0][3]+=a.x*v0.w;
            acc[0][4]+=a.x*v1.x; acc[0][5]+=a.x*v1.y; acc[0][6]+=a.x*v1.z; acc[0][7]+=a.x*v1.w;
            acc[1][0]+=a.y*v0.x; acc[1][1]+=a.y*v0.y; acc[1][2]+=a.y*v0.z; acc[1][3]+=a.y*v0.w;
            acc[1][4]+=a.y*v1.x; acc[1][5]+=a.y*v1.y; acc[1][6]+=a.y*v1.z; acc[1][7]+=a.y*v1.w;
            acc[2][0]+=a.z*v0.x; acc[2][1]+=a.z*v0.y; acc[2][2]+=a.z*v0.z; acc[2][3]+=a.z*v0.w;
            acc[2][4]+=a.z*v1.x; acc[2][5]+=a.z*v1.y; acc[2][6]+=a.z*v1.z; acc[2][7]+=a.z*v1.w;
            acc[3][0]+=a.w*v0.x; acc[3][1]+=a.w*v0.y; acc[3][2]+=a.w*v0.z; acc[3][3]+=a.w*v0.w;
            acc[3][4]+=a.w*v1.x; acc[3][5]+=a.w*v1.y; acc[3][6]+=a.w*v1.z; acc[3][7]+=a.w*v1.w;
        }
        __syncthreads();
    }
    #pragma unroll
    for (int ii = 0; ii < 4; ++ii) {
        const int n = i0 + ty * 4 + ii;
        float* orow = g_outh + (size_t)(b * NN + n) * OUTD + h * VD;
        #pragma unroll
        for (int cc = 0; cc < 4; ++cc) {
            orow[tx * 4 + cc] = acc[ii][cc];                // cols 0..63 always < 124
            const int c2 = 64 + tx * 4 + cc;
            if (c2 < VD) orow[c2] = acc[ii][cc + 4];        // cols 64..123
        }
    }
}

// ---------------------------------------------------------------
// K6: out = out_head (8192x992) @ W_out^T (64x992) + b_out.
// Tile 64 rows x 64 cols, k-tile 32.
// ---------------------------------------------------------------
__global__ __launch_bounds__(256) void k_proj(const float* __restrict__ Wout,
                                              const float* __restrict__ bout,
                                              float* __restrict__ out) {
    __shared__ float Xs[32][68];   // [k][n]
    __shared__ float Ws[32][68];   // [k][m]
    const int n0 = blockIdx.x * 64;
    const int tid = threadIdx.x;
    const int ty = tid >> 4, tx = tid & 15;
    const int r = tid >> 3, c4 = (tid & 7) << 2;
    float acc[4][4] = {};
    for (int k0 = 0; k0 < OUTD; k0 += 32) {
        #pragma unroll
        for (int p = 0; p < 2; ++p) {
            const int rr = r + p * 32;
            float4 a = *(const float4*)&g_outh[(size_t)(n0 + rr) * OUTD + k0 + c4];
            Xs[c4+0][rr] = a.x; Xs[c4+1][rr] = a.y; Xs[c4+2][rr] = a.z; Xs[c4+3][rr] = a.w;
            float4 w = *(const float4*)&Wout[(size_t)rr * OUTD + k0 + c4];
            Ws[c4+0][rr] = w.x; Ws[c4+1][rr] = w.y; Ws[c4+2][rr] = w.z; Ws[c4+3][rr] = w.w;
        }
        __syncthreads();
        #pragma unroll
        for (int k = 0; k < 32; ++k) {
            float4 a = *(const float4*)&Xs[k][ty * 4];
            float4 b = *(const float4*)&Ws[k][tx * 4];
            acc[0][0] += a.x*b.x; acc[0][1] += a.x*b.y; acc[0][2] += a.x*b.z; acc[0][3] += a.x*b.w;
            acc[1][0] += a.y*b.x; acc[1][1] += a.y*b.y; acc[1][2] += a.y*b.z; acc[1][3] += a.y*b.w;
            acc[2][0] += a.z*b.x; acc[2][1] += a.z*b.y; acc[2][2] += a.z*b.z; acc[2][3] += a.z*b.w;
            acc[3][0] += a.w*b.x; acc[3][1] += a.w*b.y; acc[3][2] += a.w*b.z; acc[3][3] += a.w*b.w;
        }
        __syncthreads();
    }
    #pragma unroll
    for (int ii = 0; ii < 4; ++ii) {
        #pragma unroll
        for (int jj = 0; jj < 4; ++jj) {
            const int m = tx * 4 + jj;
            out[(size_t)(n0 + ty * 4 + ii) * 64 + m] = acc[ii][jj] + bout[m];
        }
    }
}

// ---------------------------------------------------------------
extern "C" void kernel_launch(void* const* d_in, const int* in_sizes, int n_in,
                              void* d_out, int out_size) {
    const float* x    = (const float*)d_in[0];
    const float* Wqk  = (const float*)d_in[1];
    const float* w1   = (const float*)d_in[2];
    const float* b1   = (const float*)d_in[3];
    const float* w2   = (const float*)d_in[4];
    const float* b2   = (const float*)d_in[5];
    const float* Wout = (const float*)d_in[6];
    const float* bout = (const float*)d_in[7];

    float* out  = (float*)d_out;
    float* attn = out + (size_t)BB * NN * DD;   // 524288 floats in, rest is attn

    k_qkproj <<<dim3(16, 128), 256>>>(x, Wqk);
    k_conv   <<<TOK, 128>>>(x, w1, b1, w2, b2);
    k_scores <<<dim3(32, 32, BH), 256>>>(attn);
    k_softmax<<<BH * NN, 256>>>(attn);
    k_av     <<<dim3(32, BH), 256>>>(attn);
    k_proj   <<<128, 256>>>(Wout, bout, out);
}

// round 7
// speedup vs baseline: 1.9755x; 1.9755x over previous
#include <cuda_runtime.h>
#include <cuda_bf16.h>
#include <cstdint>

#define BB   4
#define NN   2048
#define DD   64
#define HH   8
#define BH   (BB*HH)      // 32
#define TOK  (BB*NN)      // 8192
#define VD   124
#define OUTD (HH*VD)      // 992
#define TSTR 72           // smem tile row stride (bf16) -> 144B, ldmatrix conflict-free

// ---------------- scratch (no dynamic allocation allowed) ----------------
__device__ __align__(16) __nv_bfloat16 g_qh[(size_t)BH*NN*DD];   // 8 MB each
__device__ __align__(16) __nv_bfloat16 g_ql[(size_t)BH*NN*DD];
__device__ __align__(16) __nv_bfloat16 g_kh[(size_t)BH*NN*DD];
__device__ __align__(16) __nv_bfloat16 g_kl[(size_t)BH*NN*DD];
__device__ __align__(16) __nv_bfloat16 g_vth[(size_t)BB*128*NN]; // V^T [b][c][n], 2 MB
__device__ __align__(16) __nv_bfloat16 g_vtl[(size_t)BB*128*NN];
__device__ __align__(16) float g_outh[(size_t)TOK*OUTD];         // 32.5 MB

__device__ __forceinline__ uint32_t smem_u32(const void* p) {
    uint32_t a;
    asm("{ .reg .u64 t; cvta.to.shared.u64 t, %1; cvt.u32.u64 %0, t; }" : "=r"(a) : "l"(p));
    return a;
}
#define LDSM4(r, addr) \
    asm volatile("ldmatrix.sync.aligned.m8n8.x4.shared.b16 {%0,%1,%2,%3}, [%4];" \
        : "=r"((r)[0]), "=r"((r)[1]), "=r"((r)[2]), "=r"((r)[3]) : "r"(addr))
#define MMA_BF16(d, a, b) \
    asm volatile("mma.sync.aligned.m16n8k16.row.col.f32.bf16.bf16.f32 " \
        "{%0,%1,%2,%3}, {%4,%5,%6,%7}, {%8,%9}, {%0,%1,%2,%3};" \
        : "+f"((d)[0]), "+f"((d)[1]), "+f"((d)[2]), "+f"((d)[3]) \
        : "r"((a)[0]), "r"((a)[1]), "r"((a)[2]), "r"((a)[3]), "r"((b)[0]), "r"((b)[1]))

// ---------------------------------------------------------------
// K1: qk = x @ W_qk^T, scatter to bf16 hi/lo q/k in (b,h,n,d) layout.
// ---------------------------------------------------------------
__global__ __launch_bounds__(256) void k_qkproj(const float* __restrict__ x,
                                                const float* __restrict__ Wqk) {
    __shared__ float Xs[64][68];
    __shared__ float Ws[64][68];
    const int tid = threadIdx.x;
    const int m0 = blockIdx.x * 64;
    const int n0 = blockIdx.y * 64;
    const int r = tid >> 4, c4 = (tid & 15) << 2;
    #pragma unroll
    for (int p = 0; p < 4; ++p) {
        const int rr = r + p * 16;
        float4 a = *(const float4*)&x[(size_t)(n0 + rr) * 64 + c4];
        Xs[c4+0][rr] = a.x; Xs[c4+1][rr] = a.y; Xs[c4+2][rr] = a.z; Xs[c4+3][rr] = a.w;
        float4 w = *(const float4*)&Wqk[(size_t)(m0 + rr) * 64 + c4];
        Ws[c4+0][rr] = w.x; Ws[c4+1][rr] = w.y; Ws[c4+2][rr] = w.z; Ws[c4+3][rr] = w.w;
    }
    __syncthreads();
    const int ty = tid >> 4, tx = tid & 15;
    float acc[4][4] = {};
    #pragma unroll
    for (int d = 0; d < 64; ++d) {
        float4 a = *(const float4*)&Xs[d][ty * 4];
        float4 b = *(const float4*)&Ws[d][tx * 4];
        acc[0][0] += a.x*b.x; acc[0][1] += a.x*b.y; acc[0][2] += a.x*b.z; acc[0][3] += a.x*b.w;
        acc[1][0] += a.y*b.x; acc[1][1] += a.y*b.y; acc[1][2] += a.y*b.z; acc[1][3] += a.y*b.w;
        acc[2][0] += a.z*b.x; acc[2][1] += a.z*b.y; acc[2][2] += a.z*b.z; acc[2][3] += a.z*b.w;
        acc[3][0] += a.w*b.x; acc[3][1] += a.w*b.y; acc[3][2] += a.w*b.z; acc[3][3] += a.w*b.w;
    }
    const bool isK = (m0 >= 512);
    const int head = (isK ? m0 - 512 : m0) >> 6;
    __nv_bfloat16* dh = isK ? g_kh : g_qh;
    __nv_bfloat16* dl = isK ? g_kl : g_ql;
    #pragma unroll
    for (int ii = 0; ii < 4; ++ii) {
        const int n = n0 + ty * 4 + ii;
        const int bb = n >> 11, nl = n & 2047;
        const size_t o = ((size_t)(bb * HH + head) * NN + nl) * 64 + tx * 4;
        __nv_bfloat16 h0 = __float2bfloat16(acc[ii][0]);
        __nv_bfloat16 h1 = __float2bfloat16(acc[ii][1]);
        __nv_bfloat16 h2 = __float2bfloat16(acc[ii][2]);
        __nv_bfloat16 h3 = __float2bfloat16(acc[ii][3]);
        __nv_bfloat162 H01; H01.x = h0; H01.y = h1;
        __nv_bfloat162 H23; H23.x = h2; H23.y = h3;
        __nv_bfloat162 L01; L01.x = __float2bfloat16(acc[ii][0] - __bfloat162float(h0));
                            L01.y = __float2bfloat16(acc[ii][1] - __bfloat162float(h1));
        __nv_bfloat162 L23; L23.x = __float2bfloat16(acc[ii][2] - __bfloat162float(h2));
                            L23.y = __float2bfloat16(acc[ii][3] - __bfloat162float(h3));
        *(__nv_bfloat162*)(dh + o)     = H01;
        *(__nv_bfloat162*)(dh + o + 2) = H23;
        *(__nv_bfloat162*)(dl + o)     = L01;
        *(__nv_bfloat162*)(dl + o + 2) = L23;
    }
}

// ---------------------------------------------------------------
// K2: value conv chain -> V^T bf16 hi/lo [b][c(128,pad0)][n]
// ---------------------------------------------------------------
__global__ __launch_bounds__(128) void k_conv(const float* __restrict__ x,
                                              const float* __restrict__ w1, const float* __restrict__ b1,
                                              const float* __restrict__ w2, const float* __restrict__ b2) {
    __shared__ float xr[64];
    __shared__ float h1s[2][40];
    const int n = blockIdx.x;
    const int tid = threadIdx.x;
    if (tid < 64) xr[tid] = x[(size_t)n * 64 + tid];
    __syncthreads();
    if (tid < 80) {
        const int c = tid / 40, t = tid % 40;
        float acc = b1[c];
        #pragma unroll
        for (int k = 0; k < 25; ++k) acc += xr[t + k] * w1[c * 25 + k];
        h1s[c][t] = acc;
    }
    __syncthreads();
    float a = 0.f;
    if (tid < VD) {
        const int c2 = tid / 31, t2 = tid % 31;
        float acc = b2[c2];
        #pragma unroll
        for (int c = 0; c < 2; ++c)
            #pragma unroll
            for (int k = 0; k < 10; ++k)
                acc += h1s[c][t2 + k] * w2[(c2 * 2 + c) * 10 + k];
        a = acc;
    }
    const int bb = n >> 11, nl = n & 2047;
    __nv_bfloat16 h = __float2bfloat16(a);
    __nv_bfloat16 l = __float2bfloat16(a - __bfloat162float(h));
    const size_t o = ((size_t)bb * 128 + tid) * NN + nl;
    g_vth[o] = h;
    g_vtl[o] = l;
}

// ---------------------------------------------------------------
// K3: scores = 0.125 * Q K^T via mma.sync bf16-split. 128x128 tile/CTA.
// ---------------------------------------------------------------
__global__ __launch_bounds__(256) void k_scores_mma(float* __restrict__ attn) {
    extern __shared__ __nv_bfloat16 sm[];
    __nv_bfloat16* Qh = sm;
    __nv_bfloat16* Ql = sm + 128 * TSTR;
    __nv_bfloat16* Kh = sm + 2 * 128 * TSTR;
    __nv_bfloat16* Kl = sm + 3 * 128 * TSTR;
    const int tid = threadIdx.x, wid = tid >> 5, lane = tid & 31;
    const int bh = blockIdx.z, i0 = blockIdx.y * 128, j0 = blockIdx.x * 128;

    const __nv_bfloat16* q_h = g_qh + ((size_t)bh * NN + i0) * 64;
    const __nv_bfloat16* q_l = g_ql + ((size_t)bh * NN + i0) * 64;
    const __nv_bfloat16* k_h = g_kh + ((size_t)bh * NN + j0) * 64;
    const __nv_bfloat16* k_l = g_kl + ((size_t)bh * NN + j0) * 64;
    #pragma unroll
    for (int t = 0; t < 4; ++t) {
        const int id = tid + t * 256;
        const int r = id >> 3, c = (id & 7) * 8;
        const size_t src = (size_t)r * 64 + c;
        *(uint4*)&Qh[r * TSTR + c] = *(const uint4*)(q_h + src);
        *(uint4*)&Ql[r * TSTR + c] = *(const uint4*)(q_l + src);
        *(uint4*)&Kh[r * TSTR + c] = *(const uint4*)(k_h + src);
        *(uint4*)&Kl[r * TSTR + c] = *(const uint4*)(k_l + src);
    }
    __syncthreads();

    const int wm = wid >> 2, wn = wid & 3;
    float acc[4][4][4] = {};
    const int a_row = wm * 64 + (lane & 15);
    const int a_k   = (lane >> 4) * 8;
    const int b_row = wn * 32 + (lane & 7) + (lane >> 4) * 8;
    const int b_k   = ((lane >> 3) & 1) * 8;
    const __nv_bfloat16* Ap[3] = {Qh, Qh, Ql};
    const __nv_bfloat16* Bp[3] = {Kh, Kl, Kh};
    #pragma unroll
    for (int t = 0; t < 3; ++t) {
        const uint32_t abase = smem_u32(Ap[t] + a_row * TSTR + a_k);
        const uint32_t bbase = smem_u32(Bp[t] + b_row * TSTR + b_k);
        #pragma unroll
        for (int ks = 0; ks < 4; ++ks) {
            uint32_t af[4][4], bf[2][4];
            #pragma unroll
            for (int mt = 0; mt < 4; ++mt)
                LDSM4(af[mt], abase + (mt * 16 * TSTR + ks * 16) * 2);
            #pragma unroll
            for (int np = 0; np < 2; ++np)
                LDSM4(bf[np], bbase + (np * 16 * TSTR + ks * 16) * 2);
            #pragma unroll
            for (int mt = 0; mt < 4; ++mt)
                #pragma unroll
                for (int nt = 0; nt < 4; ++nt)
                    MMA_BF16(acc[mt][nt], af[mt], &bf[nt >> 1][(nt & 1) * 2]);
        }
    }
    const int g = lane >> 2, qd = lane & 3;
    float* ab = attn + ((size_t)(bh * NN + i0 + wm * 64 + g)) * NN + j0 + wn * 32 + qd * 2;
    #pragma unroll
    for (int mt = 0; mt < 4; ++mt)
        #pragma unroll
        for (int nt = 0; nt < 4; ++nt) {
            float2 u; u.x = acc[mt][nt][0] * 0.125f; u.y = acc[mt][nt][1] * 0.125f;
            float2 v; v.x = acc[mt][nt][2] * 0.125f; v.y = acc[mt][nt][3] * 0.125f;
            *(float2*)(ab + (size_t)(mt * 16) * NN + nt * 8)     = u;
            *(float2*)(ab + (size_t)(mt * 16 + 8) * NN + nt * 8) = v;
        }
}

// ---------------------------------------------------------------
// K4: row softmax in place, one block (256 thr) per row of 2048.
// ---------------------------------------------------------------
__global__ __launch_bounds__(256) void k_softmax(float* __restrict__ attn) {
    __shared__ float red[8];
    const size_t row = blockIdx.x;
    float* p = attn + row * (size_t)NN;
    const int tid = threadIdx.x;
    float v[8];
    #pragma unroll
    for (int e = 0; e < 8; ++e) v[e] = p[tid + e * 256];
    float m = v[0];
    #pragma unroll
    for (int e = 1; e < 8; ++e) m = fmaxf(m, v[e]);
    #pragma unroll
    for (int o = 16; o; o >>= 1) m = fmaxf(m, __shfl_xor_sync(0xffffffffu, m, o));
    if ((tid & 31) == 0) red[tid >> 5] = m;
    __syncthreads();
    float bm = red[0];
    #pragma unroll
    for (int w = 1; w < 8; ++w) bm = fmaxf(bm, red[w]);
    __syncthreads();
    float s = 0.f;
    #pragma unroll
    for (int e = 0; e < 8; ++e) { v[e] = __expf(v[e] - bm); s += v[e]; }
    #pragma unroll
    for (int o = 16; o; o >>= 1) s += __shfl_xor_sync(0xffffffffu, s, o);
    if ((tid & 31) == 0) red[tid >> 5] = s;
    __syncthreads();
    float bs = 0.f;
    #pragma unroll
    for (int w = 0; w < 8; ++w) bs += red[w];
    const float inv = 1.f / bs;
    #pragma unroll
    for (int e = 0; e < 8; ++e) p[tid + e * 256] = v[e] * inv;
}

// ---------------------------------------------------------------
// K5: out_head = P @ V^T via mma.sync bf16-split, P converted on the fly.
// 128 rows x 128 channels (124 real) per CTA, K=2048 in chunks of 64.
// ---------------------------------------------------------------
__global__ __launch_bounds__(256) void k_av_mma(const float* __restrict__ attn) {
    extern __shared__ __nv_bfloat16 sm[];
    __nv_bfloat16* Ph = sm;
    __nv_bfloat16* Pl = sm + 128 * TSTR;
    __nv_bfloat16* Vh = sm + 2 * 128 * TSTR;
    __nv_bfloat16* Vl = sm + 3 * 128 * TSTR;
    const int tid = threadIdx.x, wid = tid >> 5, lane = tid & 31;
    const int bh = blockIdx.y, bb = bh >> 3, hh = bh & 7;
    const int i0 = blockIdx.x * 128;

    const float* Prow = attn + ((size_t)bh * NN + i0) * NN;
    const __nv_bfloat16* vh = g_vth + (size_t)bb * 128 * NN;
    const __nv_bfloat16* vl = g_vtl + (size_t)bb * 128 * NN;

    const int wm = wid >> 2, wn = wid & 3;
    float acc[4][4][4] = {};
    const int a_row = wm * 64 + (lane & 15);
    const int a_k   = (lane >> 4) * 8;
    const int b_row = wn * 32 + (lane & 7) + (lane >> 4) * 8;
    const int b_k   = ((lane >> 3) & 1) * 8;

    for (int it = 0; it < 32; ++it) {
        const int k0 = it * 64;
        if (it) __syncthreads();
        // P tile: 128 rows x 64 f32 -> bf16 hi/lo
        #pragma unroll
        for (int t = 0; t < 8; ++t) {
            const int id = tid + t * 256;
            const int r = id >> 4, c = (id & 15) * 4;
            float4 f = *(const float4*)(Prow + (size_t)r * NN + k0 + c);
            __nv_bfloat16 h0 = __float2bfloat16(f.x), h1 = __float2bfloat16(f.y);
            __nv_bfloat16 h2 = __float2bfloat16(f.z), h3 = __float2bfloat16(f.w);
            __nv_bfloat162 H01; H01.x = h0; H01.y = h1;
            __nv_bfloat162 H23; H23.x = h2; H23.y = h3;
            __nv_bfloat162 L01; L01.x = __float2bfloat16(f.x - __bfloat162float(h0));
                                L01.y = __float2bfloat16(f.y - __bfloat162float(h1));
            __nv_bfloat162 L23; L23.x = __float2bfloat16(f.z - __bfloat162float(h2));
                                L23.y = __float2bfloat16(f.w - __bfloat162float(h3));
            *(__nv_bfloat162*)&Ph[r * TSTR + c]     = H01;
            *(__nv_bfloat162*)&Ph[r * TSTR + c + 2] = H23;
            *(__nv_bfloat162*)&Pl[r * TSTR + c]     = L01;
            *(__nv_bfloat162*)&Pl[r * TSTR + c + 2] = L23;
        }
        // V^T tile: 128 c-rows x 64 k bf16 hi/lo
        #pragma unroll
        for (int t = 0; t < 4; ++t) {
            const int id = tid + t * 256;
            const int r = id >> 3, c = (id & 7) * 8;
            const size_t src = (size_t)r * NN + k0 + c;
            *(uint4*)&Vh[r * TSTR + c] = *(const uint4*)(vh + src);
            *(uint4*)&Vl[r * TSTR + c] = *(const uint4*)(vl + src);
        }
        __syncthreads();

        const __nv_bfloat16* Ap[3] = {Ph, Ph, Pl};
        const __nv_bfloat16* Bp[3] = {Vh, Vl, Vh};
        #pragma unroll
        for (int t = 0; t < 3; ++t) {
            const uint32_t abase = smem_u32(Ap[t] + a_row * TSTR + a_k);
            const uint32_t bbase = smem_u32(Bp[t] + b_row * TSTR + b_k);
            #pragma unroll
            for (int ks = 0; ks < 4; ++ks) {
                uint32_t af[4][4], bf[2][4];
                #pragma unroll
                for (int mt = 0; mt < 4; ++mt)
                    LDSM4(af[mt], abase + (mt * 16 * TSTR + ks * 16) * 2);
                #pragma unroll
                for (int np = 0; np < 2; ++np)
                    LDSM4(bf[np], bbase + (np * 16 * TSTR + ks * 16) * 2);
                #pragma unroll
                for (int mt = 0; mt < 4; ++mt)
                    #pragma unroll
                    for (int nt = 0; nt < 4; ++nt)
                        MMA_BF16(acc[mt][nt], af[mt], &bf[nt >> 1][(nt & 1) * 2]);
            }
        }
    }

    const int g = lane >> 2, qd = lane & 3;
    #pragma unroll
    for (int mt = 0; mt < 4; ++mt) {
        #pragma unroll
        for (int half = 0; half < 2; ++half) {
            const int row = i0 + wm * 64 + g + mt * 16 + half * 8;
            float* orow = g_outh + (size_t)(bb * NN + row) * OUTD + hh * VD;
            #pragma unroll
            for (int nt = 0; nt < 4; ++nt) {
                const int c = wn * 32 + nt * 8 + qd * 2;
                if (c < VD) {
                    float2 u; u.x = acc[mt][nt][half * 2]; u.y = acc[mt][nt][half * 2 + 1];
                    *(float2*)(orow + c) = u;
                }
            }
        }
    }
}

// ---------------------------------------------------------------
// K6: out = out_head (8192x992) @ W_out^T (64x992) + b_out.
// ---------------------------------------------------------------
__global__ __launch_bounds__(256) void k_proj(const float* __restrict__ Wout,
                                              const float* __restrict__ bout,
                                              float* __restrict__ out) {
    __shared__ float Xs[32][68];
    __shared__ float Ws[32][68];
    const int n0 = blockIdx.x * 64;
    const int tid = threadIdx.x;
    const int ty = tid >> 4, tx = tid & 15;
    const int r = tid >> 3, c4 = (tid & 7) << 2;
    float acc[4][4] = {};
    for (int k0 = 0; k0 < OUTD; k0 += 32) {
        #pragma unroll
        for (int p = 0; p < 2; ++p) {
            const int rr = r + p * 32;
            float4 a = *(const float4*)&g_outh[(size_t)(n0 + rr) * OUTD + k0 + c4];
            Xs[c4+0][rr] = a.x; Xs[c4+1][rr] = a.y; Xs[c4+2][rr] = a.z; Xs[c4+3][rr] = a.w;
            float4 w = *(const float4*)&Wout[(size_t)rr * OUTD + k0 + c4];
            Ws[c4+0][rr] = w.x; Ws[c4+1][rr] = w.y; Ws[c4+2][rr] = w.z; Ws[c4+3][rr] = w.w;
        }
        __syncthreads();
        #pragma unroll
        for (int k = 0; k < 32; ++k) {
            float4 a = *(const float4*)&Xs[k][ty * 4];
            float4 b = *(const float4*)&Ws[k][tx * 4];
            acc[0][0] += a.x*b.x; acc[0][1] += a.x*b.y; acc[0][2] += a.x*b.z; acc[0][3] += a.x*b.w;
            acc[1][0] += a.y*b.x; acc[1][1] += a.y*b.y; acc[1][2] += a.y*b.z; acc[1][3] += a.y*b.w;
            acc[2][0] += a.z*b.x; acc[2][1] += a.z*b.y; acc[2][2] += a.z*b.z; acc[2][3] += a.z*b.w;
            acc[3][0] += a.w*b.x; acc[3][1] += a.w*b.y; acc[3][2] += a.w*b.z; acc[3][3] += a.w*b.w;
        }
        __syncthreads();
    }
    #pragma unroll
    for (int ii = 0; ii < 4; ++ii) {
        #pragma unroll
        for (int jj = 0; jj < 4; ++jj) {
            const int m = tx * 4 + jj;
            out[(size_t)(n0 + ty * 4 + ii) * 64 + m] = acc[ii][jj] + bout[m];
        }
    }
}

// ---------------------------------------------------------------
extern "C" void kernel_launch(void* const* d_in, const int* in_sizes, int n_in,
                              void* d_out, int out_size) {
    const float* x    = (const float*)d_in[0];
    const float* Wqk  = (const float*)d_in[1];
    const float* w1   = (const float*)d_in[2];
    const float* b1   = (const float*)d_in[3];
    const float* w2   = (const float*)d_in[4];
    const float* b2   = (const float*)d_in[5];
    const float* Wout = (const float*)d_in[6];
    const float* bout = (const float*)d_in[7];

    float* out  = (float*)d_out;
    float* attn = out + (size_t)BB * NN * DD;

    const int SMEMB = 4 * 128 * TSTR * 2;   // 73728 B
    cudaFuncSetAttribute(k_scores_mma, cudaFuncAttributeMaxDynamicSharedMemorySize, SMEMB);
    cudaFuncSetAttribute(k_av_mma,     cudaFuncAttributeMaxDynamicSharedMemorySize, SMEMB);

    k_qkproj    <<<dim3(16, 128), 256>>>(x, Wqk);
    k_conv      <<<TOK, 128>>>(x, w1, b1, w2, b2);
    k_scores_mma<<<dim3(16, 16, BH), 256, SMEMB>>>(attn);
    k_softmax   <<<BH * NN, 256>>>(attn);
    k_av_mma    <<<dim3(16, BH), 256, SMEMB>>>(attn);
    k_proj      <<<128, 256>>>(Wout, bout, out);
}

// round 8
// speedup vs baseline: 2.2146x; 1.1211x over previous
#include <cuda_runtime.h>
#include <cuda_bf16.h>
#include <cstdint>

#define BB   4
#define NN   2048
#define DD   64
#define HH   8
#define BH   (BB*HH)      // 32
#define TOK  (BB*NN)      // 8192
#define VD   124
#define OUTD (HH*VD)      // 992
#define TSTR 72           // smem tile row stride (bf16) -> 144B, ldmatrix conflict-free

// ---------------- scratch (no dynamic allocation allowed) ----------------
__device__ __align__(16) __nv_bfloat16 g_qh[(size_t)BH*NN*DD];
__device__ __align__(16) __nv_bfloat16 g_ql[(size_t)BH*NN*DD];
__device__ __align__(16) __nv_bfloat16 g_kh[(size_t)BH*NN*DD];
__device__ __align__(16) __nv_bfloat16 g_kl[(size_t)BH*NN*DD];
__device__ __align__(16) __nv_bfloat16 g_vth[(size_t)BB*128*NN];      // V^T [b][c][n]
__device__ __align__(16) __nv_bfloat16 g_vtl[(size_t)BB*128*NN];
__device__ __align__(16) __nv_bfloat16 g_eh[(size_t)BH*NN*NN];        // exp hi, 268 MB
__device__ __align__(16) __nv_bfloat16 g_el[(size_t)BH*NN*NN];        // exp lo, 268 MB
__device__ __align__(16) float g_psum[(size_t)BH*NN*16];              // row partial sums
__device__ __align__(16) float g_outh[(size_t)TOK*OUTD];              // 32.5 MB

__device__ __forceinline__ uint32_t smem_u32(const void* p) {
    uint32_t a;
    asm("{ .reg .u64 t; cvta.to.shared.u64 t, %1; cvt.u32.u64 %0, t; }" : "=r"(a) : "l"(p));
    return a;
}
#define LDSM4(r, addr) \
    asm volatile("ldmatrix.sync.aligned.m8n8.x4.shared.b16 {%0,%1,%2,%3}, [%4];" \
        : "=r"((r)[0]), "=r"((r)[1]), "=r"((r)[2]), "=r"((r)[3]) : "r"(addr))
#define MMA_BF16(d, a, b) \
    asm volatile("mma.sync.aligned.m16n8k16.row.col.f32.bf16.bf16.f32 " \
        "{%0,%1,%2,%3}, {%4,%5,%6,%7}, {%8,%9}, {%0,%1,%2,%3};" \
        : "+f"((d)[0]), "+f"((d)[1]), "+f"((d)[2]), "+f"((d)[3]) \
        : "r"((a)[0]), "r"((a)[1]), "r"((a)[2]), "r"((a)[3]), "r"((b)[0]), "r"((b)[1]))
__device__ __forceinline__ void cp16(uint32_t dst, const void* src) {
    asm volatile("cp.async.cg.shared.global [%0], [%1], 16;" :: "r"(dst), "l"(src));
}
#define CP_COMMIT() asm volatile("cp.async.commit_group;" ::: "memory")
#define CP_WAIT1()  asm volatile("cp.async.wait_group 1;" ::: "memory")
#define CP_WAIT0()  asm volatile("cp.async.wait_group 0;" ::: "memory")

// ---------------------------------------------------------------
// K1: qk = x @ W_qk^T, scatter to bf16 hi/lo q/k in (b,h,n,d) layout.
// ---------------------------------------------------------------
__global__ __launch_bounds__(256) void k_qkproj(const float* __restrict__ x,
                                                const float* __restrict__ Wqk) {
    __shared__ float Xs[64][68];
    __shared__ float Ws[64][68];
    const int tid = threadIdx.x;
    const int m0 = blockIdx.x * 64;
    const int n0 = blockIdx.y * 64;
    const int r = tid >> 4, c4 = (tid & 15) << 2;
    #pragma unroll
    for (int p = 0; p < 4; ++p) {
        const int rr = r + p * 16;
        float4 a = *(const float4*)&x[(size_t)(n0 + rr) * 64 + c4];
        Xs[c4+0][rr] = a.x; Xs[c4+1][rr] = a.y; Xs[c4+2][rr] = a.z; Xs[c4+3][rr] = a.w;
        float4 w = *(const float4*)&Wqk[(size_t)(m0 + rr) * 64 + c4];
        Ws[c4+0][rr] = w.x; Ws[c4+1][rr] = w.y; Ws[c4+2][rr] = w.z; Ws[c4+3][rr] = w.w;
    }
    __syncthreads();
    const int ty = tid >> 4, tx = tid & 15;
    float acc[4][4] = {};
    #pragma unroll
    for (int d = 0; d < 64; ++d) {
        float4 a = *(const float4*)&Xs[d][ty * 4];
        float4 b = *(const float4*)&Ws[d][tx * 4];
        acc[0][0] += a.x*b.x; acc[0][1] += a.x*b.y; acc[0][2] += a.x*b.z; acc[0][3] += a.x*b.w;
        acc[1][0] += a.y*b.x; acc[1][1] += a.y*b.y; acc[1][2] += a.y*b.z; acc[1][3] += a.y*b.w;
        acc[2][0] += a.z*b.x; acc[2][1] += a.z*b.y; acc[2][2] += a.z*b.z; acc[2][3] += a.z*b.w;
        acc[3][0] += a.w*b.x; acc[3][1] += a.w*b.y; acc[3][2] += a.w*b.z; acc[3][3] += a.w*b.w;
    }
    const bool isK = (m0 >= 512);
    const int head = (isK ? m0 - 512 : m0) >> 6;
    __nv_bfloat16* dh = isK ? g_kh : g_qh;
    __nv_bfloat16* dl = isK ? g_kl : g_ql;
    #pragma unroll
    for (int ii = 0; ii < 4; ++ii) {
        const int n = n0 + ty * 4 + ii;
        const int bb = n >> 11, nl = n & 2047;
        const size_t o = ((size_t)(bb * HH + head) * NN + nl) * 64 + tx * 4;
        __nv_bfloat16 h0 = __float2bfloat16(acc[ii][0]);
        __nv_bfloat16 h1 = __float2bfloat16(acc[ii][1]);
        __nv_bfloat16 h2 = __float2bfloat16(acc[ii][2]);
        __nv_bfloat16 h3 = __float2bfloat16(acc[ii][3]);
        __nv_bfloat162 H01; H01.x = h0; H01.y = h1;
        __nv_bfloat162 H23; H23.x = h2; H23.y = h3;
        __nv_bfloat162 L01; L01.x = __float2bfloat16(acc[ii][0] - __bfloat162float(h0));
                            L01.y = __float2bfloat16(acc[ii][1] - __bfloat162float(h1));
        __nv_bfloat162 L23; L23.x = __float2bfloat16(acc[ii][2] - __bfloat162float(h2));
                            L23.y = __float2bfloat16(acc[ii][3] - __bfloat162float(h3));
        *(__nv_bfloat162*)(dh + o)     = H01;
        *(__nv_bfloat162*)(dh + o + 2) = H23;
        *(__nv_bfloat162*)(dl + o)     = L01;
        *(__nv_bfloat162*)(dl + o + 2) = L23;
    }
}

// ---------------------------------------------------------------
// K2: value conv chain -> V^T bf16 hi/lo [b][c(128,pad0)][n]
// ---------------------------------------------------------------
__global__ __launch_bounds__(128) void k_conv(const float* __restrict__ x,
                                              const float* __restrict__ w1, const float* __restrict__ b1,
                                              const float* __restrict__ w2, const float* __restrict__ b2) {
    __shared__ float xr[64];
    __shared__ float h1s[2][40];
    const int n = blockIdx.x;
    const int tid = threadIdx.x;
    if (tid < 64) xr[tid] = x[(size_t)n * 64 + tid];
    __syncthreads();
    if (tid < 80) {
        const int c = tid / 40, t = tid % 40;
        float acc = b1[c];
        #pragma unroll
        for (int k = 0; k < 25; ++k) acc += xr[t + k] * w1[c * 25 + k];
        h1s[c][t] = acc;
    }
    __syncthreads();
    float a = 0.f;
    if (tid < VD) {
        const int c2 = tid / 31, t2 = tid % 31;
        float acc = b2[c2];
        #pragma unroll
        for (int c = 0; c < 2; ++c)
            #pragma unroll
            for (int k = 0; k < 10; ++k)
                acc += h1s[c][t2 + k] * w2[(c2 * 2 + c) * 10 + k];
        a = acc;
    }
    const int bb = n >> 11, nl = n & 2047;
    __nv_bfloat16 h = __float2bfloat16(a);
    __nv_bfloat16 l = __float2bfloat16(a - __bfloat162float(h));
    const size_t o = ((size_t)bb * 128 + tid) * NN + nl;
    g_vth[o] = h;
    g_vtl[o] = l;
}

// ---------------------------------------------------------------
// K3: E = exp(0.125 * Q K^T) via mma.sync bf16-split, 128x128 tile/CTA.
// Writes E as bf16 hi/lo to g_eh/g_el + per-row partial sums (one slot/jtile).
// ---------------------------------------------------------------
__global__ __launch_bounds__(256) void k_scores_mma() {
    extern __shared__ __nv_bfloat16 sm[];
    __shared__ float ssum[128][4];
    __nv_bfloat16* Qh = sm;
    __nv_bfloat16* Ql = sm + 128 * TSTR;
    __nv_bfloat16* Kh = sm + 2 * 128 * TSTR;
    __nv_bfloat16* Kl = sm + 3 * 128 * TSTR;
    const int tid = threadIdx.x, wid = tid >> 5, lane = tid & 31;
    const int bh = blockIdx.z, i0 = blockIdx.y * 128, j0 = blockIdx.x * 128;

    const __nv_bfloat16* q_h = g_qh + ((size_t)bh * NN + i0) * 64;
    const __nv_bfloat16* q_l = g_ql + ((size_t)bh * NN + i0) * 64;
    const __nv_bfloat16* k_h = g_kh + ((size_t)bh * NN + j0) * 64;
    const __nv_bfloat16* k_l = g_kl + ((size_t)bh * NN + j0) * 64;
    #pragma unroll
    for (int t = 0; t < 4; ++t) {
        const int id = tid + t * 256;
        const int r = id >> 3, c = (id & 7) * 8;
        const size_t src = (size_t)r * 64 + c;
        *(uint4*)&Qh[r * TSTR + c] = *(const uint4*)(q_h + src);
        *(uint4*)&Ql[r * TSTR + c] = *(const uint4*)(q_l + src);
        *(uint4*)&Kh[r * TSTR + c] = *(const uint4*)(k_h + src);
        *(uint4*)&Kl[r * TSTR + c] = *(const uint4*)(k_l + src);
    }
    __syncthreads();

    const int wm = wid >> 2, wn = wid & 3;
    float acc[4][4][4] = {};
    const int a_row = wm * 64 + (lane & 15);
    const int a_k   = (lane >> 4) * 8;
    const int b_row = wn * 32 + (lane & 7) + (lane >> 4) * 8;
    const int b_k   = ((lane >> 3) & 1) * 8;
    const uint32_t aQh = smem_u32(Qh + a_row * TSTR + a_k);
    const uint32_t aQl = smem_u32(Ql + a_row * TSTR + a_k);
    const uint32_t bKh = smem_u32(Kh + b_row * TSTR + b_k);
    const uint32_t bKl = smem_u32(Kl + b_row * TSTR + b_k);
    #pragma unroll
    for (int ks = 0; ks < 4; ++ks) {
        uint32_t ah[4][4], al[4][4], bhf[2][4], blf[2][4];
        #pragma unroll
        for (int mt = 0; mt < 4; ++mt) {
            LDSM4(ah[mt], aQh + (mt * 16 * TSTR + ks * 16) * 2);
            LDSM4(al[mt], aQl + (mt * 16 * TSTR + ks * 16) * 2);
        }
        #pragma unroll
        for (int np = 0; np < 2; ++np) {
            LDSM4(bhf[np], bKh + (np * 16 * TSTR + ks * 16) * 2);
            LDSM4(blf[np], bKl + (np * 16 * TSTR + ks * 16) * 2);
        }
        #pragma unroll
        for (int mt = 0; mt < 4; ++mt)
            #pragma unroll
            for (int nt = 0; nt < 4; ++nt) {
                MMA_BF16(acc[mt][nt], ah[mt], &bhf[nt >> 1][(nt & 1) * 2]);
                MMA_BF16(acc[mt][nt], ah[mt], &blf[nt >> 1][(nt & 1) * 2]);
                MMA_BF16(acc[mt][nt], al[mt], &bhf[nt >> 1][(nt & 1) * 2]);
            }
    }

    // epilogue: exp, hi/lo split write, per-row partial sums
    const int g = lane >> 2, qd = lane & 3;
    float rsum[8] = {};   // [mt*2+half]
    #pragma unroll
    for (int mt = 0; mt < 4; ++mt)
        #pragma unroll
        for (int nt = 0; nt < 4; ++nt) {
            float e0 = __expf(acc[mt][nt][0] * 0.125f);
            float e1 = __expf(acc[mt][nt][1] * 0.125f);
            float e2 = __expf(acc[mt][nt][2] * 0.125f);
            float e3 = __expf(acc[mt][nt][3] * 0.125f);
            rsum[mt * 2 + 0] += e0 + e1;
            rsum[mt * 2 + 1] += e2 + e3;
            const int col = j0 + wn * 32 + nt * 8 + qd * 2;
            const size_t r0 = (size_t)bh * NN + i0 + wm * 64 + mt * 16 + g;
            __nv_bfloat16 h0 = __float2bfloat16(e0), h1 = __float2bfloat16(e1);
            __nv_bfloat16 h2 = __float2bfloat16(e2), h3 = __float2bfloat16(e3);
            __nv_bfloat162 H0; H0.x = h0; H0.y = h1;
            __nv_bfloat162 H1; H1.x = h2; H1.y = h3;
            __nv_bfloat162 L0; L0.x = __float2bfloat16(e0 - __bfloat162float(h0));
                               L0.y = __float2bfloat16(e1 - __bfloat162float(h1));
            __nv_bfloat162 L1; L1.x = __float2bfloat16(e2 - __bfloat162float(h2));
                               L1.y = __float2bfloat16(e3 - __bfloat162float(h3));
            *(__nv_bfloat162*)(g_eh + r0 * NN + col)          = H0;
            *(__nv_bfloat162*)(g_eh + (r0 + 8) * NN + col)    = H1;
            *(__nv_bfloat162*)(g_el + r0 * NN + col)          = L0;
            *(__nv_bfloat162*)(g_el + (r0 + 8) * NN + col)    = L1;
        }
    #pragma unroll
    for (int e = 0; e < 8; ++e) {
        rsum[e] += __shfl_xor_sync(0xffffffffu, rsum[e], 1);
        rsum[e] += __shfl_xor_sync(0xffffffffu, rsum[e], 2);
    }
    if (qd == 0) {
        #pragma unroll
        for (int e = 0; e < 8; ++e)
            ssum[wm * 64 + (e >> 1) * 16 + (e & 1) * 8 + g][wn] = rsum[e];
    }
    __syncthreads();
    if (tid < 128) {
        float s = ssum[tid][0] + ssum[tid][1] + ssum[tid][2] + ssum[tid][3];
        g_psum[((size_t)bh * NN + i0 + tid) * 16 + blockIdx.x] = s;
    }
}

// ---------------------------------------------------------------
// K5: O' = E @ V^T (unnormalized) via cp.async double-buffered mma.sync;
// scales rows by 1/sum in epilogue; writes normalized attn fp32 on the fly.
// ---------------------------------------------------------------
__global__ __launch_bounds__(256) void k_av_mma(float* __restrict__ attn) {
    extern __shared__ __nv_bfloat16 sm[];
    __shared__ float sinv[128];
    const int TILE = 128 * TSTR;              // bf16 elems per tile
    const int tid = threadIdx.x, wid = tid >> 5, lane = tid & 31;
    const int bh = blockIdx.y, bb = bh >> 3, hh = bh & 7;
    const int i0 = blockIdx.x * 128;

    if (tid < 128) {
        const float* ps = g_psum + ((size_t)bh * NN + i0 + tid) * 16;
        float s = 0.f;
        #pragma unroll
        for (int j = 0; j < 16; ++j) s += ps[j];
        sinv[tid] = 1.f / s;
    }

    const size_t ebase = ((size_t)bh * NN + i0) * NN;
    const size_t vbase = (size_t)bb * 128 * NN;
    const uint32_t smb = smem_u32(sm);

    // fill(slot, k0): Eh,El,Vh,Vl 128x64 tiles via cp.async
    auto fill = [&](int slot, int k0) {
        const uint32_t base = smb + slot * (4 * TILE) * 2;
        #pragma unroll
        for (int t = 0; t < 4; ++t) {
            const int id = tid + t * 256;
            const int r = id >> 3, c = (id & 7) * 8;
            const uint32_t d = base + (r * TSTR + c) * 2;
            const size_t es = ebase + (size_t)r * NN + k0 + c;
            const size_t vs = vbase + (size_t)r * NN + k0 + c;
            cp16(d,                 g_eh + es);
            cp16(d + TILE * 2,      g_el + es);
            cp16(d + 2 * TILE * 2,  g_vth + vs);
            cp16(d + 3 * TILE * 2,  g_vtl + vs);
        }
        CP_COMMIT();
    };

    fill(0, 0);
    fill(1, 64);

    const int wm = wid >> 2, wn = wid & 3;
    float acc[4][4][4] = {};
    const int a_row = wm * 64 + (lane & 15);
    const int a_k   = (lane >> 4) * 8;
    const int b_row = wn * 32 + (lane & 7) + (lane >> 4) * 8;
    const int b_k   = ((lane >> 3) & 1) * 8;

    for (int it = 0; it < 32; ++it) {
        const int slot = it & 1;
        const int k0 = it * 64;
        __nv_bfloat16* Eh = sm + slot * 4 * TILE;
        __nv_bfloat16* El = Eh + TILE;
        __nv_bfloat16* Vh = Eh + 2 * TILE;
        __nv_bfloat16* Vl = Eh + 3 * TILE;
        if (it == 31) CP_WAIT0(); else CP_WAIT1();
        __syncthreads();

        // normalized attn write from smem (overlaps MMA issue below across iters)
        #pragma unroll
        for (int t = 0; t < 8; ++t) {
            const int id = tid + t * 256;
            const int r = id >> 4, c = (id & 15) * 4;
            __nv_bfloat162 h0 = *(__nv_bfloat162*)&Eh[r * TSTR + c];
            __nv_bfloat162 h1 = *(__nv_bfloat162*)&Eh[r * TSTR + c + 2];
            __nv_bfloat162 l0 = *(__nv_bfloat162*)&El[r * TSTR + c];
            __nv_bfloat162 l1 = *(__nv_bfloat162*)&El[r * TSTR + c + 2];
            const float inv = sinv[r];
            float4 o;
            o.x = (__bfloat162float(h0.x) + __bfloat162float(l0.x)) * inv;
            o.y = (__bfloat162float(h0.y) + __bfloat162float(l0.y)) * inv;
            o.z = (__bfloat162float(h1.x) + __bfloat162float(l1.x)) * inv;
            o.w = (__bfloat162float(h1.y) + __bfloat162float(l1.y)) * inv;
            *(float4*)(attn + ebase + (size_t)r * NN + k0 + c) = o;
        }

        const uint32_t aEh = smem_u32(Eh + a_row * TSTR + a_k);
        const uint32_t aEl = smem_u32(El + a_row * TSTR + a_k);
        const uint32_t bVh = smem_u32(Vh + b_row * TSTR + b_k);
        const uint32_t bVl = smem_u32(Vl + b_row * TSTR + b_k);
        #pragma unroll
        for (int ks = 0; ks < 4; ++ks) {
            uint32_t ah[4][4], al[4][4], bhf[2][4], blf[2][4];
            #pragma unroll
            for (int mt = 0; mt < 4; ++mt) {
                LDSM4(ah[mt], aEh + (mt * 16 * TSTR + ks * 16) * 2);
                LDSM4(al[mt], aEl + (mt * 16 * TSTR + ks * 16) * 2);
            }
            #pragma unroll
            for (int np = 0; np < 2; ++np) {
                LDSM4(bhf[np], bVh + (np * 16 * TSTR + ks * 16) * 2);
                LDSM4(blf[np], bVl + (np * 16 * TSTR + ks * 16) * 2);
            }
            #pragma unroll
            for (int mt = 0; mt < 4; ++mt)
                #pragma unroll
                for (int nt = 0; nt < 4; ++nt) {
                    MMA_BF16(acc[mt][nt], ah[mt], &bhf[nt >> 1][(nt & 1) * 2]);
                    MMA_BF16(acc[mt][nt], ah[mt], &blf[nt >> 1][(nt & 1) * 2]);
                    MMA_BF16(acc[mt][nt], al[mt], &bhf[nt >> 1][(nt & 1) * 2]);
                }
        }
        __syncthreads();
        if (it + 2 < 32) fill(slot, (it + 2) * 64);
    }

    const int g = lane >> 2, qd = lane & 3;
    #pragma unroll
    for (int mt = 0; mt < 4; ++mt) {
        #pragma unroll
        for (int half = 0; half < 2; ++half) {
            const int rl = wm * 64 + mt * 16 + half * 8 + g;
            const float inv = sinv[rl];
            float* orow = g_outh + (size_t)(bb * NN + i0 + rl) * OUTD + hh * VD;
            #pragma unroll
            for (int nt = 0; nt < 4; ++nt) {
                const int c = wn * 32 + nt * 8 + qd * 2;
                if (c < VD) {
                    float2 u;
                    u.x = acc[mt][nt][half * 2]     * inv;
                    u.y = acc[mt][nt][half * 2 + 1] * inv;
                    *(float2*)(orow + c) = u;
                }
            }
        }
    }
}

// ---------------------------------------------------------------
// K6: out = out_head (8192x992) @ W_out^T (64x992) + b_out.
// ---------------------------------------------------------------
__global__ __launch_bounds__(256) void k_proj(const float* __restrict__ Wout,
                                              const float* __restrict__ bout,
                                              float* __restrict__ out) {
    __shared__ float Xs[32][68];
    __shared__ float Ws[32][68];
    const int n0 = blockIdx.x * 64;
    const int tid = threadIdx.x;
    const int ty = tid >> 4, tx = tid & 15;
    const int r = tid >> 3, c4 = (tid & 7) << 2;
    float acc[4][4] = {};
    for (int k0 = 0; k0 < OUTD; k0 += 32) {
        #pragma unroll
        for (int p = 0; p < 2; ++p) {
            const int rr = r + p * 32;
            float4 a = *(const float4*)&g_outh[(size_t)(n0 + rr) * OUTD + k0 + c4];
            Xs[c4+0][rr] = a.x; Xs[c4+1][rr] = a.y; Xs[c4+2][rr] = a.z; Xs[c4+3][rr] = a.w;
            float4 w = *(const float4*)&Wout[(size_t)rr * OUTD + k0 + c4];
            Ws[c4+0][rr] = w.x; Ws[c4+1][rr] = w.y; Ws[c4+2][rr] = w.z; Ws[c4+3][rr] = w.w;
        }
        __syncthreads();
        #pragma unroll
        for (int k = 0; k < 32; ++k) {
            float4 a = *(const float4*)&Xs[k][ty * 4];
            float4 b = *(const float4*)&Ws[k][tx * 4];
            acc[0][0] += a.x*b.x; acc[0][1] += a.x*b.y; acc[0][2] += a.x*b.z; acc[0][3] += a.x*b.w;
            acc[1][0] += a.y*b.x; acc[1][1] += a.y*b.y; acc[1][2] += a.y*b.z; acc[1][3] += a.y*b.w;
            acc[2][0] += a.z*b.x; acc[2][1] += a.z*b.y; acc[2][2] += a.z*b.z; acc[2][3] += a.z*b.w;
            acc[3][0] += a.w*b.x; acc[3][1] += a.w*b.y; acc[3][2] += a.w*b.z; acc[3][3] += a.w*b.w;
        }
        __syncthreads();
    }
    #pragma unroll
    for (int ii = 0; ii < 4; ++ii) {
        #pragma unroll
        for (int jj = 0; jj < 4; ++jj) {
            const int m = tx * 4 + jj;
            out[(size_t)(n0 + ty * 4 + ii) * 64 + m] = acc[ii][jj] + bout[m];
        }
    }
}

// ---------------------------------------------------------------
extern "C" void kernel_launch(void* const* d_in, const int* in_sizes, int n_in,
                              void* d_out, int out_size) {
    const float* x    = (const float*)d_in[0];
    const float* Wqk  = (const float*)d_in[1];
    const float* w1   = (const float*)d_in[2];
    const float* b1   = (const float*)d_in[3];
    const float* w2   = (const float*)d_in[4];
    const float* b2   = (const float*)d_in[5];
    const float* Wout = (const float*)d_in[6];
    const float* bout = (const float*)d_in[7];

    float* out  = (float*)d_out;
    float* attn = out + (size_t)BB * NN * DD;

    const int SM_SC = 4 * 128 * TSTR * 2;       // 73728 B
    const int SM_AV = 2 * 4 * 128 * TSTR * 2;   // 147456 B
    cudaFuncSetAttribute(k_scores_mma, cudaFuncAttributeMaxDynamicSharedMemorySize, SM_SC);
    cudaFuncSetAttribute(k_av_mma,     cudaFuncAttributeMaxDynamicSharedMemorySize, SM_AV);

    k_qkproj    <<<dim3(16, 128), 256>>>(x, Wqk);
    k_conv      <<<TOK, 128>>>(x, w1, b1, w2, b2);
    k_scores_mma<<<dim3(16, 16, BH), 256, SM_SC>>>();
    k_av_mma    <<<dim3(16, BH), 256, SM_AV>>>(attn);
    k_proj      <<<128, 256>>>(Wout, bout, out);
}

// round 10
// speedup vs baseline: 2.2945x; 1.0361x over previous
#include <cuda_runtime.h>
#include <cuda_bf16.h>
#include <cstdint>

#define BB   4
#define NN   2048
#define DD   64
#define HH   8
#define BH   (BB*HH)      // 32
#define TOK  (BB*NN)      // 8192
#define VD   124
#define OUTD (HH*VD)      // 992
#define TSTR 72           // scores smem stride (bf16): 144B, ldmatrix conflict-free
#define TS2  40           // av smem stride for 32-col tiles: 80B, 5*16B, 5 coprime 8

// ---------------- scratch (no dynamic allocation allowed) ----------------
__device__ __align__(16) __nv_bfloat16 g_qh[(size_t)BH*NN*DD];
__device__ __align__(16) __nv_bfloat16 g_ql[(size_t)BH*NN*DD];
__device__ __align__(16) __nv_bfloat16 g_kh[(size_t)BH*NN*DD];
__device__ __align__(16) __nv_bfloat16 g_kl[(size_t)BH*NN*DD];
__device__ __align__(16) __nv_bfloat16 g_vth[(size_t)BB*128*NN];      // V^T [b][c][n]
__device__ __align__(16) __nv_bfloat16 g_vtl[(size_t)BB*128*NN];
__device__ __align__(16) __nv_bfloat16 g_eh[(size_t)BH*NN*NN];        // exp hi
__device__ __align__(16) __nv_bfloat16 g_el[(size_t)BH*NN*NN];        // exp lo
__device__ __align__(16) float g_psum[(size_t)BH*NN*16];              // row partial sums
__device__ __align__(16) float g_outh[(size_t)TOK*OUTD];

__device__ __forceinline__ uint32_t smem_u32(const void* p) {
    uint32_t a;
    asm("{ .reg .u64 t; cvta.to.shared.u64 t, %1; cvt.u32.u64 %0, t; }" : "=r"(a) : "l"(p));
    return a;
}
#define LDSM4(r, addr) \
    asm volatile("ldmatrix.sync.aligned.m8n8.x4.shared.b16 {%0,%1,%2,%3}, [%4];" \
        : "=r"((r)[0]), "=r"((r)[1]), "=r"((r)[2]), "=r"((r)[3]) : "r"(addr))
#define MMA_BF16(d, a, b) \
    asm volatile("mma.sync.aligned.m16n8k16.row.col.f32.bf16.bf16.f32 " \
        "{%0,%1,%2,%3}, {%4,%5,%6,%7}, {%8,%9}, {%0,%1,%2,%3};" \
        : "+f"((d)[0]), "+f"((d)[1]), "+f"((d)[2]), "+f"((d)[3]) \
        : "r"((a)[0]), "r"((a)[1]), "r"((a)[2]), "r"((a)[3]), "r"((b)[0]), "r"((b)[1]))
__device__ __forceinline__ void cp16(uint32_t dst, const void* src) {
    asm volatile("cp.async.cg.shared.global [%0], [%1], 16;" :: "r"(dst), "l"(src));
}
#define CP_COMMIT() asm volatile("cp.async.commit_group;" ::: "memory")
#define CP_WAIT1()  asm volatile("cp.async.wait_group 1;" ::: "memory")
#define CP_WAIT0()  asm volatile("cp.async.wait_group 0;" ::: "memory")

// ---------------------------------------------------------------
// K1: qk = x @ W_qk^T, scatter to bf16 hi/lo q/k in (b,h,n,d) layout.
// ---------------------------------------------------------------
__global__ __launch_bounds__(256) void k_qkproj(const float* __restrict__ x,
                                                const float* __restrict__ Wqk) {
    __shared__ float Xs[64][68];
    __shared__ float Ws[64][68];
    const int tid = threadIdx.x;
    const int m0 = blockIdx.x * 64;
    const int n0 = blockIdx.y * 64;
    const int r = tid >> 4, c4 = (tid & 15) << 2;
    #pragma unroll
    for (int p = 0; p < 4; ++p) {
        const int rr = r + p * 16;
        float4 a = *(const float4*)&x[(size_t)(n0 + rr) * 64 + c4];
        Xs[c4+0][rr] = a.x; Xs[c4+1][rr] = a.y; Xs[c4+2][rr] = a.z; Xs[c4+3][rr] = a.w;
        float4 w = *(const float4*)&Wqk[(size_t)(m0 + rr) * 64 + c4];
        Ws[c4+0][rr] = w.x; Ws[c4+1][rr] = w.y; Ws[c4+2][rr] = w.z; Ws[c4+3][rr] = w.w;
    }
    __syncthreads();
    const int ty = tid >> 4, tx = tid & 15;
    float acc[4][4] = {};
    #pragma unroll
    for (int d = 0; d < 64; ++d) {
        float4 a = *(const float4*)&Xs[d][ty * 4];
        float4 b = *(const float4*)&Ws[d][tx * 4];
        acc[0][0] += a.x*b.x; acc[0][1] += a.x*b.y; acc[0][2] += a.x*b.z; acc[0][3] += a.x*b.w;
        acc[1][0] += a.y*b.x; acc[1][1] += a.y*b.y; acc[1][2] += a.y*b.z; acc[1][3] += a.y*b.w;
        acc[2][0] += a.z*b.x; acc[2][1] += a.z*b.y; acc[2][2] += a.z*b.z; acc[2][3] += a.z*b.w;
        acc[3][0] += a.w*b.x; acc[3][1] += a.w*b.y; acc[3][2] += a.w*b.z; acc[3][3] += a.w*b.w;
    }
    const bool isK = (m0 >= 512);
    const int head = (isK ? m0 - 512 : m0) >> 6;
    __nv_bfloat16* dh = isK ? g_kh : g_qh;
    __nv_bfloat16* dl = isK ? g_kl : g_ql;
    #pragma unroll
    for (int ii = 0; ii < 4; ++ii) {
        const int n = n0 + ty * 4 + ii;
        const int bb = n >> 11, nl = n & 2047;
        const size_t o = ((size_t)(bb * HH + head) * NN + nl) * 64 + tx * 4;
        __nv_bfloat16 h0 = __float2bfloat16(acc[ii][0]);
        __nv_bfloat16 h1 = __float2bfloat16(acc[ii][1]);
        __nv_bfloat16 h2 = __float2bfloat16(acc[ii][2]);
        __nv_bfloat16 h3 = __float2bfloat16(acc[ii][3]);
        __nv_bfloat162 H01; H01.x = h0; H01.y = h1;
        __nv_bfloat162 H23; H23.x = h2; H23.y = h3;
        __nv_bfloat162 L01; L01.x = __float2bfloat16(acc[ii][0] - __bfloat162float(h0));
                            L01.y = __float2bfloat16(acc[ii][1] - __bfloat162float(h1));
        __nv_bfloat162 L23; L23.x = __float2bfloat16(acc[ii][2] - __bfloat162float(h2));
                            L23.y = __float2bfloat16(acc[ii][3] - __bfloat162float(h3));
        *(__nv_bfloat162*)(dh + o)     = H01;
        *(__nv_bfloat162*)(dh + o + 2) = H23;
        *(__nv_bfloat162*)(dl + o)     = L01;
        *(__nv_bfloat162*)(dl + o + 2) = L23;
    }
}

// ---------------------------------------------------------------
// K2: value conv chain -> V^T bf16 hi/lo [b][c(128,pad0)][n]
// ---------------------------------------------------------------
__global__ __launch_bounds__(128) void k_conv(const float* __restrict__ x,
                                              const float* __restrict__ w1, const float* __restrict__ b1,
                                              const float* __restrict__ w2, const float* __restrict__ b2) {
    __shared__ float xr[64];
    __shared__ float h1s[2][40];
    const int n = blockIdx.x;
    const int tid = threadIdx.x;
    if (tid < 64) xr[tid] = x[(size_t)n * 64 + tid];
    __syncthreads();
    if (tid < 80) {
        const int c = tid / 40, t = tid % 40;
        float acc = b1[c];
        #pragma unroll
        for (int k = 0; k < 25; ++k) acc += xr[t + k] * w1[c * 25 + k];
        h1s[c][t] = acc;
    }
    __syncthreads();
    float a = 0.f;
    if (tid < VD) {
        const int c2 = tid / 31, t2 = tid % 31;
        float acc = b2[c2];
        #pragma unroll
        for (int c = 0; c < 2; ++c)
            #pragma unroll
            for (int k = 0; k < 10; ++k)
                acc += h1s[c][t2 + k] * w2[(c2 * 2 + c) * 10 + k];
        a = acc;
    }
    const int bb = n >> 11, nl = n & 2047;
    __nv_bfloat16 h = __float2bfloat16(a);
    __nv_bfloat16 l = __float2bfloat16(a - __bfloat162float(h));
    const size_t o = ((size_t)bb * 128 + tid) * NN + nl;
    g_vth[o] = h;
    g_vtl[o] = l;
}

// ---------------------------------------------------------------
// K3: E = exp(0.125 * Q K^T) via mma.sync bf16-split, 128x128 tile/CTA.
// Writes E as bf16 hi/lo to g_eh/g_el + per-row partial sums (one slot/jtile).
// ---------------------------------------------------------------
__global__ __launch_bounds__(256) void k_scores_mma() {
    extern __shared__ __nv_bfloat16 sm[];
    __shared__ float ssum[128][4];
    __nv_bfloat16* Qh = sm;
    __nv_bfloat16* Ql = sm + 128 * TSTR;
    __nv_bfloat16* Kh = sm + 2 * 128 * TSTR;
    __nv_bfloat16* Kl = sm + 3 * 128 * TSTR;
    const int tid = threadIdx.x, wid = tid >> 5, lane = tid & 31;
    const int bh = blockIdx.z, i0 = blockIdx.y * 128, j0 = blockIdx.x * 128;

    const __nv_bfloat16* q_h = g_qh + ((size_t)bh * NN + i0) * 64;
    const __nv_bfloat16* q_l = g_ql + ((size_t)bh * NN + i0) * 64;
    const __nv_bfloat16* k_h = g_kh + ((size_t)bh * NN + j0) * 64;
    const __nv_bfloat16* k_l = g_kl + ((size_t)bh * NN + j0) * 64;
    #pragma unroll
    for (int t = 0; t < 4; ++t) {
        const int id = tid + t * 256;
        const int r = id >> 3, c = (id & 7) * 8;
        const size_t src = (size_t)r * 64 + c;
        *(uint4*)&Qh[r * TSTR + c] = *(const uint4*)(q_h + src);
        *(uint4*)&Ql[r * TSTR + c] = *(const uint4*)(q_l + src);
        *(uint4*)&Kh[r * TSTR + c] = *(const uint4*)(k_h + src);
        *(uint4*)&Kl[r * TSTR + c] = *(const uint4*)(k_l + src);
    }
    __syncthreads();

    const int wm = wid >> 2, wn = wid & 3;
    float acc[4][4][4] = {};
    const int a_row = wm * 64 + (lane & 15);
    const int a_k   = (lane >> 4) * 8;
    const int b_row = wn * 32 + (lane & 7) + (lane >> 4) * 8;
    const int b_k   = ((lane >> 3) & 1) * 8;
    const uint32_t aQh = smem_u32(Qh + a_row * TSTR + a_k);
    const uint32_t aQl = smem_u32(Ql + a_row * TSTR + a_k);
    const uint32_t bKh = smem_u32(Kh + b_row * TSTR + b_k);
    const uint32_t bKl = smem_u32(Kl + b_row * TSTR + b_k);
    #pragma unroll
    for (int ks = 0; ks < 4; ++ks) {
        uint32_t ah[4][4], al[4][4], bhf[2][4], blf[2][4];
        #pragma unroll
        for (int mt = 0; mt < 4; ++mt) {
            LDSM4(ah[mt], aQh + (mt * 16 * TSTR + ks * 16) * 2);
            LDSM4(al[mt], aQl + (mt * 16 * TSTR + ks * 16) * 2);
        }
        #pragma unroll
        for (int np = 0; np < 2; ++np) {
            LDSM4(bhf[np], bKh + (np * 16 * TSTR + ks * 16) * 2);
            LDSM4(blf[np], bKl + (np * 16 * TSTR + ks * 16) * 2);
        }
        #pragma unroll
        for (int mt = 0; mt < 4; ++mt)
            #pragma unroll
            for (int nt = 0; nt < 4; ++nt) {
                MMA_BF16(acc[mt][nt], ah[mt], &bhf[nt >> 1][(nt & 1) * 2]);
                MMA_BF16(acc[mt][nt], ah[mt], &blf[nt >> 1][(nt & 1) * 2]);
                MMA_BF16(acc[mt][nt], al[mt], &bhf[nt >> 1][(nt & 1) * 2]);
            }
    }

    // epilogue: exp, hi/lo split write, per-row partial sums
    const int g = lane >> 2, qd = lane & 3;
    float rsum[8] = {};
    #pragma unroll
    for (int mt = 0; mt < 4; ++mt)
        #pragma unroll
        for (int nt = 0; nt < 4; ++nt) {
            float e0 = __expf(acc[mt][nt][0] * 0.125f);
            float e1 = __expf(acc[mt][nt][1] * 0.125f);
            float e2 = __expf(acc[mt][nt][2] * 0.125f);
            float e3 = __expf(acc[mt][nt][3] * 0.125f);
            rsum[mt * 2 + 0] += e0 + e1;
            rsum[mt * 2 + 1] += e2 + e3;
            const int col = j0 + wn * 32 + nt * 8 + qd * 2;
            const size_t r0 = (size_t)bh * NN + i0 + wm * 64 + mt * 16 + g;
            __nv_bfloat16 h0 = __float2bfloat16(e0), h1 = __float2bfloat16(e1);
            __nv_bfloat16 h2 = __float2bfloat16(e2), h3 = __float2bfloat16(e3);
            __nv_bfloat162 H0; H0.x = h0; H0.y = h1;
            __nv_bfloat162 H1; H1.x = h2; H1.y = h3;
            __nv_bfloat162 L0; L0.x = __float2bfloat16(e0 - __bfloat162float(h0));
                               L0.y = __float2bfloat16(e1 - __bfloat162float(h1));
            __nv_bfloat162 L1; L1.x = __float2bfloat16(e2 - __bfloat162float(h2));
                               L1.y = __float2bfloat16(e3 - __bfloat162float(h3));
            *(__nv_bfloat162*)(g_eh + r0 * NN + col)          = H0;
            *(__nv_bfloat162*)(g_eh + (r0 + 8) * NN + col)    = H1;
            *(__nv_bfloat162*)(g_el + r0 * NN + col)          = L0;
            *(__nv_bfloat162*)(g_el + (r0 + 8) * NN + col)    = L1;
        }
    #pragma unroll
    for (int e = 0; e < 8; ++e) {
        rsum[e] += __shfl_xor_sync(0xffffffffu, rsum[e], 1);
        rsum[e] += __shfl_xor_sync(0xffffffffu, rsum[e], 2);
    }
    if (qd == 0) {
        #pragma unroll
        for (int e = 0; e < 8; ++e)
            ssum[wm * 64 + (e >> 1) * 16 + (e & 1) * 8 + g][wn] = rsum[e];
    }
    __syncthreads();
    if (tid < 128) {
        float s = ssum[tid][0] + ssum[tid][1] + ssum[tid][2] + ssum[tid][3];
        g_psum[((size_t)bh * NN + i0 + tid) * 16 + blockIdx.x] = s;
    }
}

// ---------------------------------------------------------------
// K5: O' = E @ V^T via cp.async double-buffered mma.sync, k-chunk 32
// (smem 80KB -> 2 CTAs/SM). Row-scale by 1/sum in epilogue; writes
// normalized attn fp32 on the fly.
// ---------------------------------------------------------------
__global__ __launch_bounds__(256, 2) void k_av_mma(float* __restrict__ attn) {
    extern __shared__ __nv_bfloat16 sm[];
    __shared__ float sinv[128];
    const int TILE = 128 * TS2;               // bf16 elems per 128x32 tile
    const int tid = threadIdx.x, wid = tid >> 5, lane = tid & 31;
    const int bh = blockIdx.y, bb = bh >> 3, hh = bh & 7;
    const int i0 = blockIdx.x * 128;

    if (tid < 128) {
        const float* ps = g_psum + ((size_t)bh * NN + i0 + tid) * 16;
        float s = 0.f;
        #pragma unroll
        for (int j = 0; j < 16; ++j) s += ps[j];
        sinv[tid] = 1.f / s;
    }

    const size_t ebase = ((size_t)bh * NN + i0) * NN;
    const size_t vbase = (size_t)bb * 128 * NN;
    const uint32_t smb = smem_u32(sm);

    // fill(slot, k0): Eh,El,Vh,Vl 128x32 tiles; 512 16B chunks/tile,
    // 2 chunks per thread per tile (full coverage).
    auto fill = [&](int slot, int k0) {
        const uint32_t base = smb + slot * (4 * TILE) * 2;
        #pragma unroll
        for (int t = 0; t < 2; ++t) {
            const int id = tid + t * 256;
            const int r = id >> 2, c = (id & 3) * 8;
            const uint32_t d = base + (r * TS2 + c) * 2;
            const size_t es = ebase + (size_t)r * NN + k0 + c;
            const size_t vs = vbase + (size_t)r * NN + k0 + c;
            cp16(d,                 g_eh + es);
            cp16(d + TILE * 2,      g_el + es);
            cp16(d + 2 * TILE * 2,  g_vth + vs);
            cp16(d + 3 * TILE * 2,  g_vtl + vs);
        }
        CP_COMMIT();
    };

    fill(0, 0);
    fill(1, 32);

    const int wm = wid >> 2, wn = wid & 3;
    float acc[4][4][4] = {};
    const int a_row = wm * 64 + (lane & 15);
    const int a_k   = (lane >> 4) * 8;
    const int b_row = wn * 32 + (lane & 7) + (lane >> 4) * 8;
    const int b_k   = ((lane >> 3) & 1) * 8;

    for (int it = 0; it < 64; ++it) {
        const int slot = it & 1;
        const int k0 = it * 32;
        __nv_bfloat16* Eh = sm + slot * 4 * TILE;
        __nv_bfloat16* El = Eh + TILE;
        __nv_bfloat16* Vh = Eh + 2 * TILE;
        __nv_bfloat16* Vl = Eh + 3 * TILE;
        if (it == 63) CP_WAIT0(); else CP_WAIT1();
        __syncthreads();

        // normalized attn write from smem (128x32 fp32)
        #pragma unroll
        for (int t = 0; t < 4; ++t) {
            const int id = tid + t * 256;
            const int r = id >> 3, c = (id & 7) * 4;
            __nv_bfloat162 h0 = *(__nv_bfloat162*)&Eh[r * TS2 + c];
            __nv_bfloat162 h1 = *(__nv_bfloat162*)&Eh[r * TS2 + c + 2];
            __nv_bfloat162 l0 = *(__nv_bfloat162*)&El[r * TS2 + c];
            __nv_bfloat162 l1 = *(__nv_bfloat162*)&El[r * TS2 + c + 2];
            const float inv = sinv[r];
            float4 o;
            o.x = (__bfloat162float(h0.x) + __bfloat162float(l0.x)) * inv;
            o.y = (__bfloat162float(h0.y) + __bfloat162float(l0.y)) * inv;
            o.z = (__bfloat162float(h1.x) + __bfloat162float(l1.x)) * inv;
            o.w = (__bfloat162float(h1.y) + __bfloat162float(l1.y)) * inv;
            *(float4*)(attn + ebase + (size_t)r * NN + k0 + c) = o;
        }

        const uint32_t aEh = smem_u32(Eh + a_row * TS2 + a_k);
        const uint32_t aEl = smem_u32(El + a_row * TS2 + a_k);
        const uint32_t bVh = smem_u32(Vh + b_row * TS2 + b_k);
        const uint32_t bVl = smem_u32(Vl + b_row * TS2 + b_k);
        #pragma unroll
        for (int ks = 0; ks < 2; ++ks) {
            uint32_t ah[4][4], al[4][4], bhf[2][4], blf[2][4];
            #pragma unroll
            for (int mt = 0; mt < 4; ++mt) {
                LDSM4(ah[mt], aEh + (mt * 16 * TS2 + ks * 16) * 2);
                LDSM4(al[mt], aEl + (mt * 16 * TS2 + ks * 16) * 2);
            }
            #pragma unroll
            for (int np = 0; np < 2; ++np) {
                LDSM4(bhf[np], bVh + (np * 16 * TS2 + ks * 16) * 2);
                LDSM4(blf[np], bVl + (np * 16 * TS2 + ks * 16) * 2);
            }
            #pragma unroll
            for (int mt = 0; mt < 4; ++mt)
                #pragma unroll
                for (int nt = 0; nt < 4; ++nt) {
                    MMA_BF16(acc[mt][nt], ah[mt], &bhf[nt >> 1][(nt & 1) * 2]);
                    MMA_BF16(acc[mt][nt], ah[mt], &blf[nt >> 1][(nt & 1) * 2]);
                    MMA_BF16(acc[mt][nt], al[mt], &bhf[nt >> 1][(nt & 1) * 2]);
                }
        }
        __syncthreads();
        if (it + 2 < 64) fill(slot, (it + 2) * 32);
    }

    const int g = lane >> 2, qd = lane & 3;
    #pragma unroll
    for (int mt = 0; mt < 4; ++mt) {
        #pragma unroll
        for (int half = 0; half < 2; ++half) {
            const int rl = wm * 64 + mt * 16 + half * 8 + g;
            const float inv = sinv[rl];
            float* orow = g_outh + (size_t)(bb * NN + i0 + rl) * OUTD + hh * VD;
            #pragma unroll
            for (int nt = 0; nt < 4; ++nt) {
                const int c = wn * 32 + nt * 8 + qd * 2;
                if (c < VD) {
                    float2 u;
                    u.x = acc[mt][nt][half * 2]     * inv;
                    u.y = acc[mt][nt][half * 2 + 1] * inv;
                    *(float2*)(orow + c) = u;
                }
            }
        }
    }
}

// ---------------------------------------------------------------
// K6: out = out_head (8192x992) @ W_out^T (64x992) + b_out.
// ---------------------------------------------------------------
__global__ __launch_bounds__(256) void k_proj(const float* __restrict__ Wout,
                                              const float* __restrict__ bout,
                                              float* __restrict__ out) {
    __shared__ float Xs[32][68];
    __shared__ float Ws[32][68];
    const int n0 = blockIdx.x * 64;
    const int tid = threadIdx.x;
    const int ty = tid >> 4, tx = tid & 15;
    const int r = tid >> 3, c4 = (tid & 7) << 2;
    float acc[4][4] = {};
    for (int k0 = 0; k0 < OUTD; k0 += 32) {
        #pragma unroll
        for (int p = 0; p < 2; ++p) {
            const int rr = r + p * 32;
            float4 a = *(const float4*)&g_outh[(size_t)(n0 + rr) * OUTD + k0 + c4];
            Xs[c4+0][rr] = a.x; Xs[c4+1][rr] = a.y; Xs[c4+2][rr] = a.z; Xs[c4+3][rr] = a.w;
            float4 w = *(const float4*)&Wout[(size_t)rr * OUTD + k0 + c4];
            Ws[c4+0][rr] = w.x; Ws[c4+1][rr] = w.y; Ws[c4+2][rr] = w.z; Ws[c4+3][rr] = w.w;
        }
        __syncthreads();
        #pragma unroll
        for (int k = 0; k < 32; ++k) {
            float4 a = *(const float4*)&Xs[k][ty * 4];
            float4 b = *(const float4*)&Ws[k][tx * 4];
            acc[0][0] += a.x*b.x; acc[0][1] += a.x*b.y; acc[0][2] += a.x*b.z; acc[0][3] += a.x*b.w;
            acc[1][0] += a.y*b.x; acc[1][1] += a.y*b.y; acc[1][2] += a.y*b.z; acc[1][3] += a.y*b.w;
            acc[2][0] += a.z*b.x; acc[2][1] += a.z*b.y; acc[2][2] += a.z*b.z; acc[2][3] += a.z*b.w;
            acc[3][0] += a.w*b.x; acc[3][1] += a.w*b.y; acc[3][2] += a.w*b.z; acc[3][3] += a.w*b.w;
        }
        __syncthreads();
    }
    #pragma unroll
    for (int ii = 0; ii < 4; ++ii) {
        #pragma unroll
        for (int jj = 0; jj < 4; ++jj) {
            const int m = tx * 4 + jj;
            out[(size_t)(n0 + ty * 4 + ii) * 64 + m] = acc[ii][jj] + bout[m];
        }
    }
}

// ---------------------------------------------------------------
extern "C" void kernel_launch(void* const* d_in, const int* in_sizes, int n_in,
                              void* d_out, int out_size) {
    const float* x    = (const float*)d_in[0];
    const float* Wqk  = (const float*)d_in[1];
    const float* w1   = (const float*)d_in[2];
    const float* b1   = (const float*)d_in[3];
    const float* w2   = (const float*)d_in[4];
    const float* b2   = (const float*)d_in[5];
    const float* Wout = (const float*)d_in[6];
    const float* bout = (const float*)d_in[7];

    float* out  = (float*)d_out;
    float* attn = out + (size_t)BB * NN * DD;

    const int SM_SC = 4 * 128 * TSTR * 2;       // 73728 B
    const int SM_AV = 2 * 4 * 128 * TS2 * 2;    // 81920 B -> 2 CTAs/SM
    cudaFuncSetAttribute(k_scores_mma, cudaFuncAttributeMaxDynamicSharedMemorySize, SM_SC);
    cudaFuncSetAttribute(k_av_mma,     cudaFuncAttributeMaxDynamicSharedMemorySize, SM_AV);

    k_qkproj    <<<dim3(16, 128), 256>>>(x, Wqk);
    k_conv      <<<TOK, 128>>>(x, w1, b1, w2, b2);
    k_scores_mma<<<dim3(16, 16, BH), 256, SM_SC>>>();
    k_av_mma    <<<dim3(16, BH), 256, SM_AV>>>(attn);
    k_proj      <<<128, 256>>>(Wout, bout, out);
}

// round 11
// speedup vs baseline: 3.6910x; 1.6087x over previous
#include <cuda_runtime.h>
#include <cuda_bf16.h>
#include <cuda_fp16.h>
#include <cstdint>

#define BB   4
#define NN   2048
#define DD   64
#define HH   8
#define BH   (BB*HH)      // 32
#define TOK  (BB*NN)      // 8192
#define VD   124
#define OUTD (HH*VD)      // 992
#define TSTR 72           // smem tile row stride (16-bit elems): 144B, ldmatrix conflict-free

// ---------------- scratch (no dynamic allocation allowed) ----------------
__device__ __align__(16) __nv_bfloat16 g_qh[(size_t)BH*NN*DD];
__device__ __align__(16) __nv_bfloat16 g_ql[(size_t)BH*NN*DD];
__device__ __align__(16) __nv_bfloat16 g_kh[(size_t)BH*NN*DD];
__device__ __align__(16) __nv_bfloat16 g_kl[(size_t)BH*NN*DD];
__device__ __align__(16) __half g_vt[(size_t)BB*128*NN];              // V^T fp16 [b][c][n]
__device__ __align__(16) __half g_e[(size_t)BH*NN*NN];                // exp fp16, 268 MB
__device__ __align__(16) float g_psum[(size_t)BH*NN*16];              // row partial sums
__device__ __align__(16) float g_outh[(size_t)TOK*OUTD];

__device__ __forceinline__ uint32_t smem_u32(const void* p) {
    uint32_t a;
    asm("{ .reg .u64 t; cvta.to.shared.u64 t, %1; cvt.u32.u64 %0, t; }" : "=r"(a) : "l"(p));
    return a;
}
#define LDSM4(r, addr) \
    asm volatile("ldmatrix.sync.aligned.m8n8.x4.shared.b16 {%0,%1,%2,%3}, [%4];" \
        : "=r"((r)[0]), "=r"((r)[1]), "=r"((r)[2]), "=r"((r)[3]) : "r"(addr))
#define MMA_BF16(d, a, b) \
    asm volatile("mma.sync.aligned.m16n8k16.row.col.f32.bf16.bf16.f32 " \
        "{%0,%1,%2,%3}, {%4,%5,%6,%7}, {%8,%9}, {%0,%1,%2,%3};" \
        : "+f"((d)[0]), "+f"((d)[1]), "+f"((d)[2]), "+f"((d)[3]) \
        : "r"((a)[0]), "r"((a)[1]), "r"((a)[2]), "r"((a)[3]), "r"((b)[0]), "r"((b)[1]))
#define MMA_F16(d, a, b) \
    asm volatile("mma.sync.aligned.m16n8k16.row.col.f32.f16.f16.f32 " \
        "{%0,%1,%2,%3}, {%4,%5,%6,%7}, {%8,%9}, {%0,%1,%2,%3};" \
        : "+f"((d)[0]), "+f"((d)[1]), "+f"((d)[2]), "+f"((d)[3]) \
        : "r"((a)[0]), "r"((a)[1]), "r"((a)[2]), "r"((a)[3]), "r"((b)[0]), "r"((b)[1]))
__device__ __forceinline__ void cp16(uint32_t dst, const void* src) {
    asm volatile("cp.async.cg.shared.global [%0], [%1], 16;" :: "r"(dst), "l"(src));
}
#define CP_COMMIT() asm volatile("cp.async.commit_group;" ::: "memory")
#define CP_WAIT1()  asm volatile("cp.async.wait_group 1;" ::: "memory")
#define CP_WAIT0()  asm volatile("cp.async.wait_group 0;" ::: "memory")

// ---------------------------------------------------------------
// K1: qk = x @ W_qk^T, scatter to bf16 hi/lo q/k in (b,h,n,d) layout.
// ---------------------------------------------------------------
__global__ __launch_bounds__(256) void k_qkproj(const float* __restrict__ x,
                                                const float* __restrict__ Wqk) {
    __shared__ float Xs[64][68];
    __shared__ float Ws[64][68];
    const int tid = threadIdx.x;
    const int m0 = blockIdx.x * 64;
    const int n0 = blockIdx.y * 64;
    const int r = tid >> 4, c4 = (tid & 15) << 2;
    #pragma unroll
    for (int p = 0; p < 4; ++p) {
        const int rr = r + p * 16;
        float4 a = *(const float4*)&x[(size_t)(n0 + rr) * 64 + c4];
        Xs[c4+0][rr] = a.x; Xs[c4+1][rr] = a.y; Xs[c4+2][rr] = a.z; Xs[c4+3][rr] = a.w;
        float4 w = *(const float4*)&Wqk[(size_t)(m0 + rr) * 64 + c4];
        Ws[c4+0][rr] = w.x; Ws[c4+1][rr] = w.y; Ws[c4+2][rr] = w.z; Ws[c4+3][rr] = w.w;
    }
    __syncthreads();
    const int ty = tid >> 4, tx = tid & 15;
    float acc[4][4] = {};
    #pragma unroll
    for (int d = 0; d < 64; ++d) {
        float4 a = *(const float4*)&Xs[d][ty * 4];
        float4 b = *(const float4*)&Ws[d][tx * 4];
        acc[0][0] += a.x*b.x; acc[0][1] += a.x*b.y; acc[0][2] += a.x*b.z; acc[0][3] += a.x*b.w;
        acc[1][0] += a.y*b.x; acc[1][1] += a.y*b.y; acc[1][2] += a.y*b.z; acc[1][3] += a.y*b.w;
        acc[2][0] += a.z*b.x; acc[2][1] += a.z*b.y; acc[2][2] += a.z*b.z; acc[2][3] += a.z*b.w;
        acc[3][0] += a.w*b.x; acc[3][1] += a.w*b.y; acc[3][2] += a.w*b.z; acc[3][3] += a.w*b.w;
    }
    const bool isK = (m0 >= 512);
    const int head = (isK ? m0 - 512 : m0) >> 6;
    __nv_bfloat16* dh = isK ? g_kh : g_qh;
    __nv_bfloat16* dl = isK ? g_kl : g_ql;
    #pragma unroll
    for (int ii = 0; ii < 4; ++ii) {
        const int n = n0 + ty * 4 + ii;
        const int bb = n >> 11, nl = n & 2047;
        const size_t o = ((size_t)(bb * HH + head) * NN + nl) * 64 + tx * 4;
        __nv_bfloat16 h0 = __float2bfloat16(acc[ii][0]);
        __nv_bfloat16 h1 = __float2bfloat16(acc[ii][1]);
        __nv_bfloat16 h2 = __float2bfloat16(acc[ii][2]);
        __nv_bfloat16 h3 = __float2bfloat16(acc[ii][3]);
        __nv_bfloat162 H01; H01.x = h0; H01.y = h1;
        __nv_bfloat162 H23; H23.x = h2; H23.y = h3;
        __nv_bfloat162 L01; L01.x = __float2bfloat16(acc[ii][0] - __bfloat162float(h0));
                            L01.y = __float2bfloat16(acc[ii][1] - __bfloat162float(h1));
        __nv_bfloat162 L23; L23.x = __float2bfloat16(acc[ii][2] - __bfloat162float(h2));
                            L23.y = __float2bfloat16(acc[ii][3] - __bfloat162float(h3));
        *(__nv_bfloat162*)(dh + o)     = H01;
        *(__nv_bfloat162*)(dh + o + 2) = H23;
        *(__nv_bfloat162*)(dl + o)     = L01;
        *(__nv_bfloat162*)(dl + o + 2) = L23;
    }
}

// ---------------------------------------------------------------
// K2: value conv chain -> V^T fp16 [b][c(128,pad0)][n]
// ---------------------------------------------------------------
__global__ __launch_bounds__(128) void k_conv(const float* __restrict__ x,
                                              const float* __restrict__ w1, const float* __restrict__ b1,
                                              const float* __restrict__ w2, const float* __restrict__ b2) {
    __shared__ float xr[64];
    __shared__ float h1s[2][40];
    const int n = blockIdx.x;
    const int tid = threadIdx.x;
    if (tid < 64) xr[tid] = x[(size_t)n * 64 + tid];
    __syncthreads();
    if (tid < 80) {
        const int c = tid / 40, t = tid % 40;
        float acc = b1[c];
        #pragma unroll
        for (int k = 0; k < 25; ++k) acc += xr[t + k] * w1[c * 25 + k];
        h1s[c][t] = acc;
    }
    __syncthreads();
    float a = 0.f;
    if (tid < VD) {
        const int c2 = tid / 31, t2 = tid % 31;
        float acc = b2[c2];
        #pragma unroll
        for (int c = 0; c < 2; ++c)
            #pragma unroll
            for (int k = 0; k < 10; ++k)
                acc += h1s[c][t2 + k] * w2[(c2 * 2 + c) * 10 + k];
        a = acc;
    }
    const int bb = n >> 11, nl = n & 2047;
    g_vt[((size_t)bb * 128 + tid) * NN + nl] = __float2half(a);
}

// ---------------------------------------------------------------
// K3: E = exp(0.125 * Q K^T) via mma.sync bf16-split, 128x128 tile/CTA.
// Writes E as single fp16 to g_e + per-row partial sums (one slot/jtile).
// ---------------------------------------------------------------
__global__ __launch_bounds__(256) void k_scores_mma() {
    extern __shared__ __nv_bfloat16 sm[];
    __shared__ float ssum[128][4];
    __nv_bfloat16* Qh = sm;
    __nv_bfloat16* Ql = sm + 128 * TSTR;
    __nv_bfloat16* Kh = sm + 2 * 128 * TSTR;
    __nv_bfloat16* Kl = sm + 3 * 128 * TSTR;
    const int tid = threadIdx.x, wid = tid >> 5, lane = tid & 31;
    const int bh = blockIdx.z, i0 = blockIdx.y * 128, j0 = blockIdx.x * 128;

    const __nv_bfloat16* q_h = g_qh + ((size_t)bh * NN + i0) * 64;
    const __nv_bfloat16* q_l = g_ql + ((size_t)bh * NN + i0) * 64;
    const __nv_bfloat16* k_h = g_kh + ((size_t)bh * NN + j0) * 64;
    const __nv_bfloat16* k_l = g_kl + ((size_t)bh * NN + j0) * 64;
    #pragma unroll
    for (int t = 0; t < 4; ++t) {
        const int id = tid + t * 256;
        const int r = id >> 3, c = (id & 7) * 8;
        const size_t src = (size_t)r * 64 + c;
        *(uint4*)&Qh[r * TSTR + c] = *(const uint4*)(q_h + src);
        *(uint4*)&Ql[r * TSTR + c] = *(const uint4*)(q_l + src);
        *(uint4*)&Kh[r * TSTR + c] = *(const uint4*)(k_h + src);
        *(uint4*)&Kl[r * TSTR + c] = *(const uint4*)(k_l + src);
    }
    __syncthreads();

    const int wm = wid >> 2, wn = wid & 3;
    float acc[4][4][4] = {};
    const int a_row = wm * 64 + (lane & 15);
    const int a_k   = (lane >> 4) * 8;
    const int b_row = wn * 32 + (lane & 7) + (lane >> 4) * 8;
    const int b_k   = ((lane >> 3) & 1) * 8;
    const uint32_t aQh = smem_u32(Qh + a_row * TSTR + a_k);
    const uint32_t aQl = smem_u32(Ql + a_row * TSTR + a_k);
    const uint32_t bKh = smem_u32(Kh + b_row * TSTR + b_k);
    const uint32_t bKl = smem_u32(Kl + b_row * TSTR + b_k);
    #pragma unroll
    for (int ks = 0; ks < 4; ++ks) {
        uint32_t ah[4][4], al[4][4], bhf[2][4], blf[2][4];
        #pragma unroll
        for (int mt = 0; mt < 4; ++mt) {
            LDSM4(ah[mt], aQh + (mt * 16 * TSTR + ks * 16) * 2);
            LDSM4(al[mt], aQl + (mt * 16 * TSTR + ks * 16) * 2);
        }
        #pragma unroll
        for (int np = 0; np < 2; ++np) {
            LDSM4(bhf[np], bKh + (np * 16 * TSTR + ks * 16) * 2);
            LDSM4(blf[np], bKl + (np * 16 * TSTR + ks * 16) * 2);
        }
        #pragma unroll
        for (int mt = 0; mt < 4; ++mt)
            #pragma unroll
            for (int nt = 0; nt < 4; ++nt) {
                MMA_BF16(acc[mt][nt], ah[mt], &bhf[nt >> 1][(nt & 1) * 2]);
                MMA_BF16(acc[mt][nt], ah[mt], &blf[nt >> 1][(nt & 1) * 2]);
                MMA_BF16(acc[mt][nt], al[mt], &bhf[nt >> 1][(nt & 1) * 2]);
            }
    }

    // epilogue: exp, fp16 write, per-row partial sums
    const int g = lane >> 2, qd = lane & 3;
    float rsum[8] = {};
    #pragma unroll
    for (int mt = 0; mt < 4; ++mt)
        #pragma unroll
        for (int nt = 0; nt < 4; ++nt) {
            float e0 = __expf(acc[mt][nt][0] * 0.125f);
            float e1 = __expf(acc[mt][nt][1] * 0.125f);
            float e2 = __expf(acc[mt][nt][2] * 0.125f);
            float e3 = __expf(acc[mt][nt][3] * 0.125f);
            rsum[mt * 2 + 0] += e0 + e1;
            rsum[mt * 2 + 1] += e2 + e3;
            const int col = j0 + wn * 32 + nt * 8 + qd * 2;
            const size_t r0 = (size_t)bh * NN + i0 + wm * 64 + mt * 16 + g;
            *(__half2*)(g_e + r0 * NN + col)       = __floats2half2_rn(e0, e1);
            *(__half2*)(g_e + (r0 + 8) * NN + col) = __floats2half2_rn(e2, e3);
        }
    #pragma unroll
    for (int e = 0; e < 8; ++e) {
        rsum[e] += __shfl_xor_sync(0xffffffffu, rsum[e], 1);
        rsum[e] += __shfl_xor_sync(0xffffffffu, rsum[e], 2);
    }
    if (qd == 0) {
        #pragma unroll
        for (int e = 0; e < 8; ++e)
            ssum[wm * 64 + (e >> 1) * 16 + (e & 1) * 8 + g][wn] = rsum[e];
    }
    __syncthreads();
    if (tid < 128) {
        float s = ssum[tid][0] + ssum[tid][1] + ssum[tid][2] + ssum[tid][3];
        g_psum[((size_t)bh * NN + i0 + tid) * 16 + blockIdx.x] = s;
    }
}

// ---------------------------------------------------------------
// K5: O' = E @ V^T, single fp16 MMA, cp.async double-buffered, k-chunk 64.
// smem 73.7KB -> 2 CTAs/SM. Row-scale by 1/sum; writes normalized attn fp32.
// ---------------------------------------------------------------
__global__ __launch_bounds__(256, 2) void k_av_mma(float* __restrict__ attn) {
    extern __shared__ __half smh[];
    __shared__ float sinv[128];
    const int TILE = 128 * TSTR;              // fp16 elems per 128x64 tile (stride 72)
    const int tid = threadIdx.x, wid = tid >> 5, lane = tid & 31;
    const int bh = blockIdx.y, bb = bh >> 3, hh = bh & 7;
    const int i0 = blockIdx.x * 128;

    if (tid < 128) {
        const float* ps = g_psum + ((size_t)bh * NN + i0 + tid) * 16;
        float s = 0.f;
        #pragma unroll
        for (int j = 0; j < 16; ++j) s += ps[j];
        sinv[tid] = 1.f / s;
    }

    const size_t ebase = ((size_t)bh * NN + i0) * NN;
    const size_t vbase = (size_t)bb * 128 * NN;
    const uint32_t smb = smem_u32(smh);

    // fill(slot, k0): E and V 128x64 fp16 tiles; 1024 chunks/tile, 4/thread
    auto fill = [&](int slot, int k0) {
        const uint32_t base = smb + slot * (2 * TILE) * 2;
        #pragma unroll
        for (int t = 0; t < 4; ++t) {
            const int id = tid + t * 256;
            const int r = id >> 3, c = (id & 7) * 8;
            const uint32_t d = base + (r * TSTR + c) * 2;
            cp16(d,            g_e  + ebase + (size_t)r * NN + k0 + c);
            cp16(d + TILE * 2, g_vt + vbase + (size_t)r * NN + k0 + c);
        }
        CP_COMMIT();
    };

    fill(0, 0);
    fill(1, 64);

    const int wm = wid >> 2, wn = wid & 3;
    float acc[4][4][4] = {};
    const int a_row = wm * 64 + (lane & 15);
    const int a_k   = (lane >> 4) * 8;
    const int b_row = wn * 32 + (lane & 7) + (lane >> 4) * 8;
    const int b_k   = ((lane >> 3) & 1) * 8;

    for (int it = 0; it < 32; ++it) {
        const int slot = it & 1;
        const int k0 = it * 64;
        __half* Es = smh + slot * 2 * TILE;
        __half* Vs = Es + TILE;
        if (it == 31) CP_WAIT0(); else CP_WAIT1();
        __syncthreads();

        // normalized attn write from smem (128x64 fp32)
        #pragma unroll
        for (int t = 0; t < 8; ++t) {
            const int id = tid + t * 256;
            const int r = id >> 4, c = (id & 15) * 4;
            __half2 h0 = *(__half2*)&Es[r * TSTR + c];
            __half2 h1 = *(__half2*)&Es[r * TSTR + c + 2];
            float2 f0 = __half22float2(h0);
            float2 f1 = __half22float2(h1);
            const float inv = sinv[r];
            float4 o;
            o.x = f0.x * inv; o.y = f0.y * inv;
            o.z = f1.x * inv; o.w = f1.y * inv;
            *(float4*)(attn + ebase + (size_t)r * NN + k0 + c) = o;
        }

        const uint32_t aE = smem_u32(Es + a_row * TSTR + a_k);
        const uint32_t bV = smem_u32(Vs + b_row * TSTR + b_k);
        #pragma unroll
        for (int ks = 0; ks < 4; ++ks) {
            uint32_t af[4][4], bf[2][4];
            #pragma unroll
            for (int mt = 0; mt < 4; ++mt)
                LDSM4(af[mt], aE + (mt * 16 * TSTR + ks * 16) * 2);
            #pragma unroll
            for (int np = 0; np < 2; ++np)
                LDSM4(bf[np], bV + (np * 16 * TSTR + ks * 16) * 2);
            #pragma unroll
            for (int mt = 0; mt < 4; ++mt)
                #pragma unroll
                for (int nt = 0; nt < 4; ++nt)
                    MMA_F16(acc[mt][nt], af[mt], &bf[nt >> 1][(nt & 1) * 2]);
        }
        __syncthreads();
        if (it + 2 < 32) fill(slot, (it + 2) * 64);
    }

    const int g = lane >> 2, qd = lane & 3;
    #pragma unroll
    for (int mt = 0; mt < 4; ++mt) {
        #pragma unroll
        for (int half = 0; half < 2; ++half) {
            const int rl = wm * 64 + mt * 16 + half * 8 + g;
            const float inv = sinv[rl];
            float* orow = g_outh + (size_t)(bb * NN + i0 + rl) * OUTD + hh * VD;
            #pragma unroll
            for (int nt = 0; nt < 4; ++nt) {
                const int c = wn * 32 + nt * 8 + qd * 2;
                if (c < VD) {
                    float2 u;
                    u.x = acc[mt][nt][half * 2]     * inv;
                    u.y = acc[mt][nt][half * 2 + 1] * inv;
                    *(float2*)(orow + c) = u;
                }
            }
        }
    }
}

// ---------------------------------------------------------------
// K6: out = out_head (8192x992) @ W_out^T (64x992) + b_out.
// ---------------------------------------------------------------
__global__ __launch_bounds__(256) void k_proj(const float* __restrict__ Wout,
                                              const float* __restrict__ bout,
                                              float* __restrict__ out) {
    __shared__ float Xs[32][68];
    __shared__ float Ws[32][68];
    const int n0 = blockIdx.x * 64;
    const int tid = threadIdx.x;
    const int ty = tid >> 4, tx = tid & 15;
    const int r = tid >> 3, c4 = (tid & 7) << 2;
    float acc[4][4] = {};
    for (int k0 = 0; k0 < OUTD; k0 += 32) {
        #pragma unroll
        for (int p = 0; p < 2; ++p) {
            const int rr = r + p * 32;
            float4 a = *(const float4*)&g_outh[(size_t)(n0 + rr) * OUTD + k0 + c4];
            Xs[c4+0][rr] = a.x; Xs[c4+1][rr] = a.y; Xs[c4+2][rr] = a.z; Xs[c4+3][rr] = a.w;
            float4 w = *(const float4*)&Wout[(size_t)rr * OUTD + k0 + c4];
            Ws[c4+0][rr] = w.x; Ws[c4+1][rr] = w.y; Ws[c4+2][rr] = w.z; Ws[c4+3][rr] = w.w;
        }
        __syncthreads();
        #pragma unroll
        for (int k = 0; k < 32; ++k) {
            float4 a = *(const float4*)&Xs[k][ty * 4];
            float4 b = *(const float4*)&Ws[k][tx * 4];
            acc[0][0] += a.x*b.x; acc[0][1] += a.x*b.y; acc[0][2] += a.x*b.z; acc[0][3] += a.x*b.w;
            acc[1][0] += a.y*b.x; acc[1][1] += a.y*b.y; acc[1][2] += a.y*b.z; acc[1][3] += a.y*b.w;
            acc[2][0] += a.z*b.x; acc[2][1] += a.z*b.y; acc[2][2] += a.z*b.z; acc[2][3] += a.z*b.w;
            acc[3][0] += a.w*b.x; acc[3][1] += a.w*b.y; acc[3][2] += a.w*b.z; acc[3][3] += a.w*b.w;
        }
        __syncthreads();
    }
    #pragma unroll
    for (int ii = 0; ii < 4; ++ii) {
        #pragma unroll
        for (int jj = 0; jj < 4; ++jj) {
            const int m = tx * 4 + jj;
            out[(size_t)(n0 + ty * 4 + ii) * 64 + m] = acc[ii][jj] + bout[m];
        }
    }
}

// ---------------------------------------------------------------
extern "C" void kernel_launch(void* const* d_in, const int* in_sizes, int n_in,
                              void* d_out, int out_size) {
    const float* x    = (const float*)d_in[0];
    const float* Wqk  = (const float*)d_in[1];
    const float* w1   = (const float*)d_in[2];
    const float* b1   = (const float*)d_in[3];
    const float* w2   = (const float*)d_in[4];
    const float* b2   = (const float*)d_in[5];
    const float* Wout = (const float*)d_in[6];
    const float* bout = (const float*)d_in[7];

    float* out  = (float*)d_out;
    float* attn = out + (size_t)BB * NN * DD;

    const int SM_SC = 4 * 128 * TSTR * 2;       // 73728 B
    const int SM_AV = 2 * 2 * 128 * TSTR * 2;   // 73728 B -> 2 CTAs/SM
    cudaFuncSetAttribute(k_scores_mma, cudaFuncAttributeMaxDynamicSharedMemorySize, SM_SC);
    cudaFuncSetAttribute(k_av_mma,     cudaFuncAttributeMaxDynamicSharedMemorySize, SM_AV);

    k_qkproj    <<<dim3(16, 128), 256>>>(x, Wqk);
    k_conv      <<<TOK, 128>>>(x, w1, b1, w2, b2);
    k_scores_mma<<<dim3(16, 16, BH), 256, SM_SC>>>();
    k_av_mma    <<<dim3(16, BH), 256, SM_AV>>>(attn);
    k_proj      <<<128, 256>>>(Wout, bout, out);
}

// round 12
// speedup vs baseline: 4.0853x; 1.1068x over previous
#include <cuda_runtime.h>
#include <cuda_bf16.h>
#include <cuda_fp16.h>
#include <cstdint>

#define BB   4
#define NN   2048
#define DD   64
#define HH   8
#define BH   (BB*HH)      // 32
#define TOK  (BB*NN)      // 8192
#define VD   124
#define OUTD (HH*VD)      // 992
#define TSTR 72           // smem tile row stride (16-bit elems): 144B, ldmatrix conflict-free

// ---------------- scratch (no dynamic allocation allowed) ----------------
__device__ __align__(16) __half g_q[(size_t)BH*NN*DD];                // fp16 Q
__device__ __align__(16) __half g_k[(size_t)BH*NN*DD];                // fp16 K
__device__ __align__(16) __half g_vt[(size_t)BB*128*NN];              // V^T fp16 [b][c][n]
__device__ __align__(16) __half g_e[(size_t)BH*NN*NN];                // exp fp16, 268 MB
__device__ __align__(16) float g_psum[(size_t)BH*NN*16];              // row partial sums
__device__ __align__(16) float g_outh[(size_t)TOK*OUTD];

__device__ __forceinline__ uint32_t smem_u32(const void* p) {
    uint32_t a;
    asm("{ .reg .u64 t; cvta.to.shared.u64 t, %1; cvt.u32.u64 %0, t; }" : "=r"(a) : "l"(p));
    return a;
}
#define LDSM4(r, addr) \
    asm volatile("ldmatrix.sync.aligned.m8n8.x4.shared.b16 {%0,%1,%2,%3}, [%4];" \
        : "=r"((r)[0]), "=r"((r)[1]), "=r"((r)[2]), "=r"((r)[3]) : "r"(addr))
#define MMA_F16(d, a, b) \
    asm volatile("mma.sync.aligned.m16n8k16.row.col.f32.f16.f16.f32 " \
        "{%0,%1,%2,%3}, {%4,%5,%6,%7}, {%8,%9}, {%0,%1,%2,%3};" \
        : "+f"((d)[0]), "+f"((d)[1]), "+f"((d)[2]), "+f"((d)[3]) \
        : "r"((a)[0]), "r"((a)[1]), "r"((a)[2]), "r"((a)[3]), "r"((b)[0]), "r"((b)[1]))
__device__ __forceinline__ void cp16(uint32_t dst, const void* src) {
    asm volatile("cp.async.cg.shared.global [%0], [%1], 16;" :: "r"(dst), "l"(src));
}
#define CP_COMMIT() asm volatile("cp.async.commit_group;" ::: "memory")
#define CP_WAIT1()  asm volatile("cp.async.wait_group 1;" ::: "memory")
#define CP_WAIT0()  asm volatile("cp.async.wait_group 0;" ::: "memory")

// ---------------------------------------------------------------
// K1: qk = x @ W_qk^T (fp32 compute), scatter fp16 q/k in (b,h,n,d) layout.
// ---------------------------------------------------------------
__global__ __launch_bounds__(256) void k_qkproj(const float* __restrict__ x,
                                                const float* __restrict__ Wqk) {
    __shared__ float Xs[64][68];
    __shared__ float Ws[64][68];
    const int tid = threadIdx.x;
    const int m0 = blockIdx.x * 64;
    const int n0 = blockIdx.y * 64;
    const int r = tid >> 4, c4 = (tid & 15) << 2;
    #pragma unroll
    for (int p = 0; p < 4; ++p) {
        const int rr = r + p * 16;
        float4 a = *(const float4*)&x[(size_t)(n0 + rr) * 64 + c4];
        Xs[c4+0][rr] = a.x; Xs[c4+1][rr] = a.y; Xs[c4+2][rr] = a.z; Xs[c4+3][rr] = a.w;
        float4 w = *(const float4*)&Wqk[(size_t)(m0 + rr) * 64 + c4];
        Ws[c4+0][rr] = w.x; Ws[c4+1][rr] = w.y; Ws[c4+2][rr] = w.z; Ws[c4+3][rr] = w.w;
    }
    __syncthreads();
    const int ty = tid >> 4, tx = tid & 15;
    float acc[4][4] = {};
    #pragma unroll
    for (int d = 0; d < 64; ++d) {
        float4 a = *(const float4*)&Xs[d][ty * 4];
        float4 b = *(const float4*)&Ws[d][tx * 4];
        acc[0][0] += a.x*b.x; acc[0][1] += a.x*b.y; acc[0][2] += a.x*b.z; acc[0][3] += a.x*b.w;
        acc[1][0] += a.y*b.x; acc[1][1] += a.y*b.y; acc[1][2] += a.y*b.z; acc[1][3] += a.y*b.w;
        acc[2][0] += a.z*b.x; acc[2][1] += a.z*b.y; acc[2][2] += a.z*b.z; acc[2][3] += a.z*b.w;
        acc[3][0] += a.w*b.x; acc[3][1] += a.w*b.y; acc[3][2] += a.w*b.z; acc[3][3] += a.w*b.w;
    }
    const bool isK = (m0 >= 512);
    const int head = (isK ? m0 - 512 : m0) >> 6;
    __half* dst = isK ? g_k : g_q;
    #pragma unroll
    for (int ii = 0; ii < 4; ++ii) {
        const int n = n0 + ty * 4 + ii;
        const int bb = n >> 11, nl = n & 2047;
        const size_t o = ((size_t)(bb * HH + head) * NN + nl) * 64 + tx * 4;
        *(__half2*)(dst + o)     = __floats2half2_rn(acc[ii][0], acc[ii][1]);
        *(__half2*)(dst + o + 2) = __floats2half2_rn(acc[ii][2], acc[ii][3]);
    }
}

// ---------------------------------------------------------------
// K2: value conv chain -> V^T fp16 [b][c(128,pad0)][n]
// ---------------------------------------------------------------
__global__ __launch_bounds__(128) void k_conv(const float* __restrict__ x,
                                              const float* __restrict__ w1, const float* __restrict__ b1,
                                              const float* __restrict__ w2, const float* __restrict__ b2) {
    __shared__ float xr[64];
    __shared__ float h1s[2][40];
    const int n = blockIdx.x;
    const int tid = threadIdx.x;
    if (tid < 64) xr[tid] = x[(size_t)n * 64 + tid];
    __syncthreads();
    if (tid < 80) {
        const int c = tid / 40, t = tid % 40;
        float acc = b1[c];
        #pragma unroll
        for (int k = 0; k < 25; ++k) acc += xr[t + k] * w1[c * 25 + k];
        h1s[c][t] = acc;
    }
    __syncthreads();
    float a = 0.f;
    if (tid < VD) {
        const int c2 = tid / 31, t2 = tid % 31;
        float acc = b2[c2];
        #pragma unroll
        for (int c = 0; c < 2; ++c)
            #pragma unroll
            for (int k = 0; k < 10; ++k)
                acc += h1s[c][t2 + k] * w2[(c2 * 2 + c) * 10 + k];
        a = acc;
    }
    const int bb = n >> 11, nl = n & 2047;
    g_vt[((size_t)bb * 128 + tid) * NN + nl] = __float2half(a);
}

// ---------------------------------------------------------------
// K3: E = exp(0.125 * Q K^T), single fp16 MMA, 128x128 tile/CTA.
// Writes E fp16 to g_e + per-row partial sums (one slot per j-tile).
// ---------------------------------------------------------------
__global__ __launch_bounds__(256) void k_scores_mma() {
    extern __shared__ __half smsc[];
    __shared__ float ssum[128][4];
    __half* Qs = smsc;
    __half* Ks = smsc + 128 * TSTR;
    const int tid = threadIdx.x, wid = tid >> 5, lane = tid & 31;
    const int bh = blockIdx.z, i0 = blockIdx.y * 128, j0 = blockIdx.x * 128;

    const __half* q_g = g_q + ((size_t)bh * NN + i0) * 64;
    const __half* k_g = g_k + ((size_t)bh * NN + j0) * 64;
    #pragma unroll
    for (int t = 0; t < 4; ++t) {
        const int id = tid + t * 256;
        const int r = id >> 3, c = (id & 7) * 8;
        const size_t src = (size_t)r * 64 + c;
        *(uint4*)&Qs[r * TSTR + c] = *(const uint4*)(q_g + src);
        *(uint4*)&Ks[r * TSTR + c] = *(const uint4*)(k_g + src);
    }
    __syncthreads();

    const int wm = wid >> 2, wn = wid & 3;
    float acc[4][4][4] = {};
    const int a_row = wm * 64 + (lane & 15);
    const int a_k   = (lane >> 4) * 8;
    const int b_row = wn * 32 + (lane & 7) + (lane >> 4) * 8;
    const int b_k   = ((lane >> 3) & 1) * 8;
    const uint32_t aQ = smem_u32(Qs + a_row * TSTR + a_k);
    const uint32_t bK = smem_u32(Ks + b_row * TSTR + b_k);
    #pragma unroll
    for (int ks = 0; ks < 4; ++ks) {
        uint32_t af[4][4], bf[2][4];
        #pragma unroll
        for (int mt = 0; mt < 4; ++mt)
            LDSM4(af[mt], aQ + (mt * 16 * TSTR + ks * 16) * 2);
        #pragma unroll
        for (int np = 0; np < 2; ++np)
            LDSM4(bf[np], bK + (np * 16 * TSTR + ks * 16) * 2);
        #pragma unroll
        for (int mt = 0; mt < 4; ++mt)
            #pragma unroll
            for (int nt = 0; nt < 4; ++nt)
                MMA_F16(acc[mt][nt], af[mt], &bf[nt >> 1][(nt & 1) * 2]);
    }

    // epilogue: exp, fp16 write, per-row partial sums
    const int g = lane >> 2, qd = lane & 3;
    float rsum[8] = {};
    #pragma unroll
    for (int mt = 0; mt < 4; ++mt)
        #pragma unroll
        for (int nt = 0; nt < 4; ++nt) {
            float e0 = __expf(acc[mt][nt][0] * 0.125f);
            float e1 = __expf(acc[mt][nt][1] * 0.125f);
            float e2 = __expf(acc[mt][nt][2] * 0.125f);
            float e3 = __expf(acc[mt][nt][3] * 0.125f);
            rsum[mt * 2 + 0] += e0 + e1;
            rsum[mt * 2 + 1] += e2 + e3;
            const int col = j0 + wn * 32 + nt * 8 + qd * 2;
            const size_t r0 = (size_t)bh * NN + i0 + wm * 64 + mt * 16 + g;
            *(__half2*)(g_e + r0 * NN + col)       = __floats2half2_rn(e0, e1);
            *(__half2*)(g_e + (r0 + 8) * NN + col) = __floats2half2_rn(e2, e3);
        }
    #pragma unroll
    for (int e = 0; e < 8; ++e) {
        rsum[e] += __shfl_xor_sync(0xffffffffu, rsum[e], 1);
        rsum[e] += __shfl_xor_sync(0xffffffffu, rsum[e], 2);
    }
    if (qd == 0) {
        #pragma unroll
        for (int e = 0; e < 8; ++e)
            ssum[wm * 64 + (e >> 1) * 16 + (e & 1) * 8 + g][wn] = rsum[e];
    }
    __syncthreads();
    if (tid < 128) {
        float s = ssum[tid][0] + ssum[tid][1] + ssum[tid][2] + ssum[tid][3];
        g_psum[((size_t)bh * NN + i0 + tid) * 16 + blockIdx.x] = s;
    }
}

// ---------------------------------------------------------------
// K5: O' = E @ V^T, single fp16 MMA, cp.async double-buffered, k-chunk 64.
// smem 73.7KB -> 2 CTAs/SM. Row-scale by 1/sum; writes normalized attn fp32.
// ---------------------------------------------------------------
__global__ __launch_bounds__(256, 2) void k_av_mma(float* __restrict__ attn) {
    extern __shared__ __half smh[];
    __shared__ float sinv[128];
    const int TILE = 128 * TSTR;              // fp16 elems per 128x64 tile (stride 72)
    const int tid = threadIdx.x, wid = tid >> 5, lane = tid & 31;
    const int bh = blockIdx.y, bb = bh >> 3, hh = bh & 7;
    const int i0 = blockIdx.x * 128;

    if (tid < 128) {
        const float* ps = g_psum + ((size_t)bh * NN + i0 + tid) * 16;
        float s = 0.f;
        #pragma unroll
        for (int j = 0; j < 16; ++j) s += ps[j];
        sinv[tid] = 1.f / s;
    }

    const size_t ebase = ((size_t)bh * NN + i0) * NN;
    const size_t vbase = (size_t)bb * 128 * NN;
    const uint32_t smb = smem_u32(smh);

    // fill(slot, k0): E and V 128x64 fp16 tiles; 1024 chunks/tile, 4/thread
    auto fill = [&](int slot, int k0) {
        const uint32_t base = smb + slot * (2 * TILE) * 2;
        #pragma unroll
        for (int t = 0; t < 4; ++t) {
            const int id = tid + t * 256;
            const int r = id >> 3, c = (id & 7) * 8;
            const uint32_t d = base + (r * TSTR + c) * 2;
            cp16(d,            g_e  + ebase + (size_t)r * NN + k0 + c);
            cp16(d + TILE * 2, g_vt + vbase + (size_t)r * NN + k0 + c);
        }
        CP_COMMIT();
    };

    fill(0, 0);
    fill(1, 64);

    const int wm = wid >> 2, wn = wid & 3;
    float acc[4][4][4] = {};
    const int a_row = wm * 64 + (lane & 15);
    const int a_k   = (lane >> 4) * 8;
    const int b_row = wn * 32 + (lane & 7) + (lane >> 4) * 8;
    const int b_k   = ((lane >> 3) & 1) * 8;

    for (int it = 0; it < 32; ++it) {
        const int slot = it & 1;
        const int k0 = it * 64;
        __half* Es = smh + slot * 2 * TILE;
        __half* Vs = Es + TILE;
        if (it == 31) CP_WAIT0(); else CP_WAIT1();
        __syncthreads();

        // normalized attn write from smem (128x64 fp32)
        #pragma unroll
        for (int t = 0; t < 8; ++t) {
            const int id = tid + t * 256;
            const int r = id >> 4, c = (id & 15) * 4;
            __half2 h0 = *(__half2*)&Es[r * TSTR + c];
            __half2 h1 = *(__half2*)&Es[r * TSTR + c + 2];
            float2 f0 = __half22float2(h0);
            float2 f1 = __half22float2(h1);
            const float inv = sinv[r];
            float4 o;
            o.x = f0.x * inv; o.y = f0.y * inv;
            o.z = f1.x * inv; o.w = f1.y * inv;
            *(float4*)(attn + ebase + (size_t)r * NN + k0 + c) = o;
        }

        const uint32_t aE = smem_u32(Es + a_row * TSTR + a_k);
        const uint32_t bV = smem_u32(Vs + b_row * TSTR + b_k);
        #pragma unroll
        for (int ks = 0; ks < 4; ++ks) {
            uint32_t af[4][4], bf[2][4];
            #pragma unroll
            for (int mt = 0; mt < 4; ++mt)
                LDSM4(af[mt], aE + (mt * 16 * TSTR + ks * 16) * 2);
            #pragma unroll
            for (int np = 0; np < 2; ++np)
                LDSM4(bf[np], bV + (np * 16 * TSTR + ks * 16) * 2);
            #pragma unroll
            for (int mt = 0; mt < 4; ++mt)
                #pragma unroll
                for (int nt = 0; nt < 4; ++nt)
                    MMA_F16(acc[mt][nt], af[mt], &bf[nt >> 1][(nt & 1) * 2]);
        }
        __syncthreads();
        if (it + 2 < 32) fill(slot, (it + 2) * 64);
    }

    const int g = lane >> 2, qd = lane & 3;
    #pragma unroll
    for (int mt = 0; mt < 4; ++mt) {
        #pragma unroll
        for (int half = 0; half < 2; ++half) {
            const int rl = wm * 64 + mt * 16 + half * 8 + g;
            const float inv = sinv[rl];
            float* orow = g_outh + (size_t)(bb * NN + i0 + rl) * OUTD + hh * VD;
            #pragma unroll
            for (int nt = 0; nt < 4; ++nt) {
                const int c = wn * 32 + nt * 8 + qd * 2;
                if (c < VD) {
                    float2 u;
                    u.x = acc[mt][nt][half * 2]     * inv;
                    u.y = acc[mt][nt][half * 2 + 1] * inv;
                    *(float2*)(orow + c) = u;
                }
            }
        }
    }
}

// ---------------------------------------------------------------
// K6: out = out_head (8192x992) @ W_out^T (64x992) + b_out.
// ---------------------------------------------------------------
__global__ __launch_bounds__(256) void k_proj(const float* __restrict__ Wout,
                                              const float* __restrict__ bout,
                                              float* __restrict__ out) {
    __shared__ float Xs[32][68];
    __shared__ float Ws[32][68];
    const int n0 = blockIdx.x * 64;
    const int tid = threadIdx.x;
    const int ty = tid >> 4, tx = tid & 15;
    const int r = tid >> 3, c4 = (tid & 7) << 2;
    float acc[4][4] = {};
    for (int k0 = 0; k0 < OUTD; k0 += 32) {
        #pragma unroll
        for (int p = 0; p < 2; ++p) {
            const int rr = r + p * 32;
            float4 a = *(const float4*)&g_outh[(size_t)(n0 + rr) * OUTD + k0 + c4];
            Xs[c4+0][rr] = a.x; Xs[c4+1][rr] = a.y; Xs[c4+2][rr] = a.z; Xs[c4+3][rr] = a.w;
            float4 w = *(const float4*)&Wout[(size_t)rr * OUTD + k0 + c4];
            Ws[c4+0][rr] = w.x; Ws[c4+1][rr] = w.y; Ws[c4+2][rr] = w.z; Ws[c4+3][rr] = w.w;
        }
        __syncthreads();
        #pragma unroll
        for (int k = 0; k < 32; ++k) {
            float4 a = *(const float4*)&Xs[k][ty * 4];
            float4 b = *(const float4*)&Ws[k][tx * 4];
            acc[0][0] += a.x*b.x; acc[0][1] += a.x*b.y; acc[0][2] += a.x*b.z; acc[0][3] += a.x*b.w;
            acc[1][0] += a.y*b.x; acc[1][1] += a.y*b.y; acc[1][2] += a.y*b.z; acc[1][3] += a.y*b.w;
            acc[2][0] += a.z*b.x; acc[2][1] += a.z*b.y; acc[2][2] += a.z*b.z; acc[2][3] += a.z*b.w;
            acc[3][0] += a.w*b.x; acc[3][1] += a.w*b.y; acc[3][2] += a.w*b.z; acc[3][3] += a.w*b.w;
        }
        __syncthreads();
    }
    #pragma unroll
    for (int ii = 0; ii < 4; ++ii) {
        #pragma unroll
        for (int jj = 0; jj < 4; ++jj) {
            const int m = tx * 4 + jj;
            out[(size_t)(n0 + ty * 4 + ii) * 64 + m] = acc[ii][jj] + bout[m];
        }
    }
}

// ---------------------------------------------------------------
extern "C" void kernel_launch(void* const* d_in, const int* in_sizes, int n_in,
                              void* d_out, int out_size) {
    const float* x    = (const float*)d_in[0];
    const float* Wqk  = (const float*)d_in[1];
    const float* w1   = (const float*)d_in[2];
    const float* b1   = (const float*)d_in[3];
    const float* w2   = (const float*)d_in[4];
    const float* b2   = (const float*)d_in[5];
    const float* Wout = (const float*)d_in[6];
    const float* bout = (const float*)d_in[7];

    float* out  = (float*)d_out;
    float* attn = out + (size_t)BB * NN * DD;

    const int SM_SC = 2 * 128 * TSTR * 2;       // 36864 B
    const int SM_AV = 2 * 2 * 128 * TSTR * 2;   // 73728 B -> 2 CTAs/SM
    cudaFuncSetAttribute(k_scores_mma, cudaFuncAttributeMaxDynamicSharedMemorySize, SM_SC);
    cudaFuncSetAttribute(k_av_mma,     cudaFuncAttributeMaxDynamicSharedMemorySize, SM_AV);

    k_qkproj    <<<dim3(16, 128), 256>>>(x, Wqk);
    k_conv      <<<TOK, 128>>>(x, w1, b1, w2, b2);
    k_scores_mma<<<dim3(16, 16, BH), 256, SM_SC>>>();
    k_av_mma    <<<dim3(16, BH), 256, SM_AV>>>(attn);
    k_proj      <<<128, 256>>>(Wout, bout, out);
}